// round 7
// baseline (speedup 1.0000x reference)
#include <cuda_runtime.h>
#include <cuda_bf16.h>

#define NNODES 50000
#define FIN    512
#define H1N    8
#define C1N    16
#define F1     128      // H1*C1
#define F2     40
#define EMAX   800000
#define ETOTMAX (EMAX + NNODES)

// ---------------- static scratch ----------------
__device__ float g_h1 [NNODES * F1];
__device__ float g_h1a[NNODES * F1];
__device__ float g_as1[NNODES * H1N];
__device__ float g_ad1[NNODES * H1N];
__device__ float g_h2 [NNODES * F2];
__device__ float g_as2[NNODES];
__device__ float g_ad2[NNODES];
__device__ int   g_counts[NNODES];
__device__ int   g_rowptr[NNODES + 1];
__device__ int   g_cursor[NNODES];
__device__ int   g_csr[ETOTMAX];
__device__ int   g_bsum[64];

__device__ __nv_bfloat16 g_Bth[F1 * FIN];   // hi(W1) transposed  [n][k]
__device__ __nv_bfloat16 g_Btm[F1 * FIN];   // mid(W1) transposed [n][k]

// ---------------- CSR build ----------------
__global__ void k_zero_counts() {
    int i = blockIdx.x * blockDim.x + threadIdx.x;
    if (i < NNODES) g_counts[i] = 0;
}

__global__ void k_count(const int* __restrict__ ei, int E, int Etot) {
    int i = blockIdx.x * blockDim.x + threadIdx.x;
    if (i >= Etot) return;
    int d = (i < E) ? ei[E + i] : (i - E);
    if (d < 0 || d >= NNODES) return;
    atomicAdd(&g_counts[d], 1);
}

__global__ void k_scan1() {
    __shared__ int tmp[1024];
    int t = threadIdx.x;
    int gid = blockIdx.x * 1024 + t;
    int v = (gid < NNODES) ? g_counts[gid] : 0;
    tmp[t] = v;
    __syncthreads();
    for (int off = 1; off < 1024; off <<= 1) {
        int x = (t >= off) ? tmp[t - off] : 0;
        __syncthreads();
        tmp[t] += x;
        __syncthreads();
    }
    if (gid < NNODES) g_rowptr[gid] = tmp[t] - v;
    if (t == 1023) g_bsum[blockIdx.x] = tmp[1023];
}

__global__ void k_scan2(int nb) {
    if (threadIdx.x == 0) {
        int acc = 0;
        for (int i = 0; i < nb; i++) { int x = g_bsum[i]; g_bsum[i] = acc; acc += x; }
    }
}

__global__ void k_scan3(int Etot) {
    int gid = blockIdx.x * blockDim.x + threadIdx.x;
    if (gid < NNODES) {
        int v = g_rowptr[gid] + g_bsum[gid >> 10];
        g_rowptr[gid] = v;
        g_cursor[gid] = v;
    }
    if (gid == 0) g_rowptr[NNODES] = Etot;
}

__global__ void k_fill(const int* __restrict__ ei, int E, int Etot) {
    int i = blockIdx.x * blockDim.x + threadIdx.x;
    if (i >= Etot) return;
    int s, d;
    if (i < E) { s = ei[i]; d = ei[E + i]; }
    else       { s = d = i - E; }
    if (d < 0 || d >= NNODES || s < 0 || s >= NNODES) return;
    int pos = atomicAdd(&g_cursor[d], 1);
    if (pos < ETOTMAX) g_csr[pos] = s;
}

// ---------------- bf16 split of W1 (tiny: 128KB) ----------------
__global__ void k_splitB(const float* __restrict__ W1) {
    int i = blockIdx.x * blockDim.x + threadIdx.x;
    if (i >= FIN * F1) return;
    int k = i / F1, n = i % F1;
    float v = W1[i];
    __nv_bfloat16 h = __float2bfloat16_rn(v);
    __nv_bfloat16 m = __float2bfloat16_rn(v - __bfloat162float(h));
    g_Bth[n * FIN + k] = h;
    g_Btm[n * FIN + k] = m;
}

// ---------------- GEMM1 + fused coeff1 epilogue ----------------
#define SWZ32(row, chk) ((row) * 64 + (((chk) ^ (((row) >> 1) & 3)) << 4))
#define TILEB 8192   // one 128x32 bf16 tile

__device__ __forceinline__ void ldmx4(unsigned* r, unsigned addr) {
    asm volatile("ldmatrix.sync.aligned.m8n8.x4.shared.b16 {%0,%1,%2,%3}, [%4];"
                 : "=r"(r[0]), "=r"(r[1]), "=r"(r[2]), "=r"(r[3]) : "r"(addr));
}

__device__ __forceinline__ void mma16816(float* c, const unsigned* a, const unsigned* b) {
    asm volatile(
        "mma.sync.aligned.m16n8k16.row.col.f32.bf16.bf16.f32 "
        "{%0,%1,%2,%3}, {%4,%5,%6,%7}, {%8,%9}, {%0,%1,%2,%3};"
        : "+f"(c[0]), "+f"(c[1]), "+f"(c[2]), "+f"(c[3])
        : "r"(a[0]), "r"(a[1]), "r"(a[2]), "r"(a[3]), "r"(b[0]), "r"(b[1]));
}

__device__ __forceinline__ void cpasync16(unsigned saddr, const void* gaddr) {
    asm volatile("cp.async.cg.shared.global [%0], [%1], 16;"
                 :: "r"(saddr), "l"(gaddr));
}

extern __shared__ __align__(16) unsigned char dynsmem[];

__global__ __launch_bounds__(256, 2) void k_gemm1_mma(const float* __restrict__ X,
                                                      const float* __restrict__ att_s,
                                                      const float* __restrict__ att_d) {
    const int AH = 0, AM = 2 * TILEB, BH = 4 * TILEB, BMo = 6 * TILEB;
    unsigned base = (unsigned)__cvta_generic_to_shared(dynsmem);

    int tid  = threadIdx.x;
    int lane = tid & 31;
    int wid  = tid >> 5;
    int wr   = wid & 3;
    int wc   = wid >> 2;
    int bm   = blockIdx.x * 128;

    // A fp32 load mapping: 8 threads/row, 4 floats each; 4 rows/thread (+32 apart)
    int arow = tid >> 3;
    int acol = (tid & 7) * 4;
    bool av[4];
    long gA[4];
#pragma unroll
    for (int i = 0; i < 4; i++) {
        int r = bm + arow + 32 * i;
        av[i] = r < NNODES;
        gA[i] = (long)r * FIN;
    }
    unsigned aStOff = SWZ32(arow, acol >> 3) + ((acol & 4) << 1);

    // B cp.async mapping
    int lrow = tid >> 2, lchk = tid & 3;
    unsigned sBo0 = SWZ32(lrow, lchk), sBo1 = SWZ32(lrow + 64, lchk);

    // ldmatrix offsets
    int sub = lane >> 3, r8 = lane & 7;
    unsigned aOff[2][2], bOff[4][2];
#pragma unroll
    for (int mt = 0; mt < 2; mt++) {
        int row = wr * 32 + mt * 16 + (sub & 1) * 8 + r8;
#pragma unroll
        for (int ks = 0; ks < 2; ks++)
            aOff[mt][ks] = SWZ32(row, (sub >> 1) + 2 * ks);
    }
#pragma unroll
    for (int np = 0; np < 4; np++) {
        int row = wc * 64 + np * 16 + (sub >> 1) * 8 + r8;
#pragma unroll
        for (int ks = 0; ks < 2; ks++)
            bOff[np][ks] = SWZ32(row, (sub & 1) + 2 * ks);
    }

    float acc[2][8][4];
#pragma unroll
    for (int mt = 0; mt < 2; mt++)
#pragma unroll
        for (int nt = 0; nt < 8; nt++)
#pragma unroll
            for (int j = 0; j < 4; j++) acc[mt][nt][j] = 0.f;

    const int NIT = FIN / 32;   // 16

    auto issueB = [&](int it, int b) {
        int koff = it * 32;
        cpasync16(base + BH  + b * TILEB + sBo0, &g_Bth[(long)lrow * FIN + koff + lchk * 8]);
        cpasync16(base + BH  + b * TILEB + sBo1, &g_Bth[(long)(lrow + 64) * FIN + koff + lchk * 8]);
        cpasync16(base + BMo + b * TILEB + sBo0, &g_Btm[(long)lrow * FIN + koff + lchk * 8]);
        cpasync16(base + BMo + b * TILEB + sBo1, &g_Btm[(long)(lrow + 64) * FIN + koff + lchk * 8]);
    };
    auto loadA = [&](int it, float4* ra) {
        int koff = it * 32 + acol;
#pragma unroll
        for (int i = 0; i < 4; i++)
            ra[i] = av[i] ? *(const float4*)&X[gA[i] + koff]
                          : make_float4(0.f, 0.f, 0.f, 0.f);
    };

    float4 ra[4];
    issueB(0, 0);
    asm volatile("cp.async.commit_group;" ::);
    loadA(0, ra);

    for (int it = 0; it < NIT; it++) {
        int buf = it & 1;
#pragma unroll
        for (int i = 0; i < 4; i++) {
            float f[4] = {ra[i].x, ra[i].y, ra[i].z, ra[i].w};
            __nv_bfloat16 h[4], m[4];
#pragma unroll
            for (int j = 0; j < 4; j++) {
                h[j] = __float2bfloat16_rn(f[j]);
                m[j] = __float2bfloat16_rn(f[j] - __bfloat162float(h[j]));
            }
            unsigned off = aStOff + 32 * i * 64;
            *(uint2*)(dynsmem + AH + buf * TILEB + off) = *(uint2*)h;
            *(uint2*)(dynsmem + AM + buf * TILEB + off) = *(uint2*)m;
        }
        if (it + 1 < NIT) {
            loadA(it + 1, ra);
            issueB(it + 1, buf ^ 1);
            asm volatile("cp.async.commit_group;" ::);
            asm volatile("cp.async.wait_group 1;" ::);
        } else {
            asm volatile("cp.async.wait_group 0;" ::);
        }
        __syncthreads();

        unsigned ah = base + AH  + buf * TILEB;
        unsigned am = base + AM  + buf * TILEB;
        unsigned bh = base + BH  + buf * TILEB;
        unsigned bmm = base + BMo + buf * TILEB;
#pragma unroll
        for (int ks = 0; ks < 2; ks++) {
            // A fragments first (16 regs live), B streamed per-np (8 regs live)
            unsigned ahf[2][4], amf[2][4];
#pragma unroll
            for (int mt = 0; mt < 2; mt++) {
                ldmx4(ahf[mt], ah + aOff[mt][ks]);
                ldmx4(amf[mt], am + aOff[mt][ks]);
            }
#pragma unroll
            for (int np = 0; np < 4; np++) {
                unsigned bhf[4], bmf[4];
                ldmx4(bhf, bh  + bOff[np][ks]);
                ldmx4(bmf, bmm + bOff[np][ks]);
#pragma unroll
                for (int mt = 0; mt < 2; mt++)
#pragma unroll
                    for (int q = 0; q < 2; q++) {
                        int nt = np * 2 + q;
                        mma16816(acc[mt][nt], ahf[mt], &bhf[q * 2]);
                        mma16816(acc[mt][nt], amf[mt], &bhf[q * 2]);
                        mma16816(acc[mt][nt], ahf[mt], &bmf[q * 2]);
                    }
            }
        }
        __syncthreads();
    }

    int g = lane >> 2, t = lane & 3;
    // h1 writeback
#pragma unroll
    for (int mt = 0; mt < 2; mt++) {
        int r0 = bm + wr * 32 + mt * 16 + g;
        int r1 = r0 + 8;
#pragma unroll
        for (int nt = 0; nt < 8; nt++) {
            int col = wc * 64 + nt * 8 + t * 2;
            if (r0 < NNODES)
                *(float2*)&g_h1[(long)r0 * F1 + col] = make_float2(acc[mt][nt][0], acc[mt][nt][1]);
            if (r1 < NNODES)
                *(float2*)&g_h1[(long)r1 * F1 + col] = make_float2(acc[mt][nt][2], acc[mt][nt][3]);
        }
    }
    // fused coeff1: as1/ad1 per (row, head) via quad reduction.
#pragma unroll
    for (int mt = 0; mt < 2; mt++) {
        int r0 = bm + wr * 32 + mt * 16 + g;
        int r1 = r0 + 8;
#pragma unroll
        for (int hh = 0; hh < 4; hh++) {
            float s0 = 0.f, d0 = 0.f, s1 = 0.f, d1 = 0.f;
#pragma unroll
            for (int q = 0; q < 2; q++) {
                int nt  = 2 * hh + q;
                int col = wc * 64 + nt * 8 + t * 2;
                float asv0 = __ldg(&att_s[col]), asv1 = __ldg(&att_s[col + 1]);
                float adv0 = __ldg(&att_d[col]), adv1 = __ldg(&att_d[col + 1]);
                s0 += acc[mt][nt][0] * asv0 + acc[mt][nt][1] * asv1;
                d0 += acc[mt][nt][0] * adv0 + acc[mt][nt][1] * adv1;
                s1 += acc[mt][nt][2] * asv0 + acc[mt][nt][3] * asv1;
                d1 += acc[mt][nt][2] * adv0 + acc[mt][nt][3] * adv1;
            }
#pragma unroll
            for (int o = 1; o <= 2; o <<= 1) {
                s0 += __shfl_xor_sync(0xFFFFFFFFu, s0, o);
                d0 += __shfl_xor_sync(0xFFFFFFFFu, d0, o);
                s1 += __shfl_xor_sync(0xFFFFFFFFu, s1, o);
                d1 += __shfl_xor_sync(0xFFFFFFFFu, d1, o);
            }
            if (t == 0) {
                int gh = wc * 4 + hh;
                if (r0 < NNODES) { g_as1[r0 * H1N + gh] = s0; g_ad1[r0 * H1N + gh] = d0; }
                if (r1 < NNODES) { g_as1[r1 * H1N + gh] = s1; g_ad1[r1 * H1N + gh] = d1; }
            }
        }
    }
}

// ---------------- layer-1 aggregation: warp/node, pipelined online softmax --
__global__ void k_agg1(const float* __restrict__ b1) {
    int gtid = blockIdx.x * blockDim.x + threadIdx.x;
    int n    = gtid >> 5;
    int lane = threadIdx.x & 31;
    if (n >= NNODES) return;
    int h = lane >> 2;
    int beg = g_rowptr[n], end = g_rowptr[n + 1];
    float adst = g_ad1[n * H1N + h];
    float m = -1e30f, s = 0.f;
    float ax = 0.f, ay = 0.f, az = 0.f, aw = 0.f;

    int   s_p2 = (beg + 1 < end) ? __ldg(&g_csr[beg + 1]) : 0;
    float e_p1 = 0.f;
    float4 v_p1 = make_float4(0.f, 0.f, 0.f, 0.f);
    if (beg < end) {
        int s0 = __ldg(&g_csr[beg]);
        e_p1 = g_as1[s0 * H1N + h];
        v_p1 = *(const float4*)&g_h1[(long)s0 * F1 + lane * 4];
    }
    for (int j = beg; j < end; j++) {
        float  e_c = e_p1 + adst;
        float4 v   = v_p1;
        int s_nxt = s_p2;
        if (j + 2 < end) s_p2 = __ldg(&g_csr[j + 2]);
        if (j + 1 < end) {
            e_p1 = g_as1[s_nxt * H1N + h];
            v_p1 = *(const float4*)&g_h1[(long)s_nxt * F1 + lane * 4];
        }
        float e = (e_c > 0.f) ? e_c : 0.2f * e_c;
        float mnew  = fmaxf(m, e);
        float scale = __expf(m - mnew);
        float w     = __expf(e - mnew);
        s  = s  * scale + w;
        ax = ax * scale + w * v.x;
        ay = ay * scale + w * v.y;
        az = az * scale + w * v.z;
        aw = aw * scale + w * v.w;
        m = mnew;
    }
    float inv = 1.f / (s + 1e-16f);
    float o[4];
    o[0] = ax * inv + b1[lane * 4 + 0];
    o[1] = ay * inv + b1[lane * 4 + 1];
    o[2] = az * inv + b1[lane * 4 + 2];
    o[3] = aw * inv + b1[lane * 4 + 3];
#pragma unroll
    for (int i = 0; i < 4; i++)
        o[i] = (o[i] > 0.f) ? o[i] : (__expf(o[i]) - 1.f);
    *(float4*)&g_h1a[(long)n * F1 + lane * 4] = *(float4*)o;
}

// ---------------- GEMM2 + fused coeff2 ----------------
#define HP 132
__global__ __launch_bounds__(320) void k_gemm2(const float* __restrict__ W2,
                                               const float* __restrict__ att_s,
                                               const float* __restrict__ att_d) {
    __shared__ float hs [32 * HP];
    __shared__ float wst[40 * HP];
    __shared__ float h2s[32 * 41];
    int r0  = blockIdx.x * 32;
    int tid = threadIdx.x;
    for (int i = tid; i < 40 * F1; i += 320) {
        int c = i >> 7, k = i & 127;
        wst[c * HP + k] = W2[k * F2 + c];
    }
    for (int i = tid; i < 32 * F1; i += 320) {
        int r = i >> 7, k = i & 127;
        int gr = r0 + r;
        hs[r * HP + k] = (gr < NNODES) ? g_h1a[(long)gr * F1 + k] : 0.f;
    }
    __syncthreads();
    int c  = tid % 40;
    int rr = tid / 40;
    float acc[4] = {0.f, 0.f, 0.f, 0.f};
    for (int k4 = 0; k4 < F1 / 4; k4++) {
        float4 w = *(float4*)&wst[c * HP + k4 * 4];
#pragma unroll
        for (int i = 0; i < 4; i++) {
            float4 hv = *(float4*)&hs[(rr + i * 8) * HP + k4 * 4];
            acc[i] += w.x * hv.x + w.y * hv.y + w.z * hv.z + w.w * hv.w;
        }
    }
#pragma unroll
    for (int i = 0; i < 4; i++) {
        int r = rr + i * 8;
        int gr = r0 + r;
        h2s[r * 41 + c] = acc[i];
        if (gr < NNODES) g_h2[(long)gr * F2 + c] = acc[i];
    }
    __syncthreads();
    if (tid < 32) {
        int gr = r0 + tid;
        if (gr < NNODES) {
            float s = 0.f, d = 0.f;
#pragma unroll
            for (int cc = 0; cc < F2; cc++) {
                float v = h2s[tid * 41 + cc];
                s += v * __ldg(&att_s[cc]);
                d += v * __ldg(&att_d[cc]);
            }
            g_as2[gr] = s;
            g_ad2[gr] = d;
        }
    }
}

// ---------------- layer-2 aggregation + bias + log_softmax ----------------
__global__ void k_agg2(const float* __restrict__ b2, float* __restrict__ out) {
    int gtid = blockIdx.x * blockDim.x + threadIdx.x;
    int n    = gtid >> 5;
    int lane = threadIdx.x & 31;
    if (n >= NNODES) return;
    bool has2 = lane < 8;
    int beg = g_rowptr[n], end = g_rowptr[n + 1];
    float adst = g_ad2[n];
    float m = -1e30f, s = 0.f, a0 = 0.f, a1 = 0.f;

    int   s_p2 = (beg + 1 < end) ? __ldg(&g_csr[beg + 1]) : 0;
    float e_p1 = 0.f, v0_p = 0.f, v1_p = 0.f;
    if (beg < end) {
        int s0 = __ldg(&g_csr[beg]);
        e_p1 = g_as2[s0];
        v0_p = g_h2[(long)s0 * F2 + lane];
        v1_p = has2 ? g_h2[(long)s0 * F2 + 32 + lane] : 0.f;
    }
    for (int j = beg; j < end; j++) {
        float e_c = e_p1 + adst;
        float v0 = v0_p, v1 = v1_p;
        int s_nxt = s_p2;
        if (j + 2 < end) s_p2 = __ldg(&g_csr[j + 2]);
        if (j + 1 < end) {
            e_p1 = g_as2[s_nxt];
            v0_p = g_h2[(long)s_nxt * F2 + lane];
            v1_p = has2 ? g_h2[(long)s_nxt * F2 + 32 + lane] : 0.f;
        }
        float e = (e_c > 0.f) ? e_c : 0.2f * e_c;
        float mnew  = fmaxf(m, e);
        float scale = __expf(m - mnew);
        float w     = __expf(e - mnew);
        s  = s  * scale + w;
        a0 = a0 * scale + w * v0;
        a1 = a1 * scale + w * v1;
        m = mnew;
    }
    float inv = 1.f / (s + 1e-16f);
    float x0 = a0 * inv + b2[lane];
    float x1 = has2 ? (a1 * inv + b2[32 + lane]) : -1e30f;
    float mx = fmaxf(x0, x1);
#pragma unroll
    for (int o = 16; o; o >>= 1) mx = fmaxf(mx, __shfl_xor_sync(0xFFFFFFFFu, mx, o));
    float se = __expf(x0 - mx) + (has2 ? __expf(x1 - mx) : 0.f);
#pragma unroll
    for (int o = 16; o; o >>= 1) se += __shfl_xor_sync(0xFFFFFFFFu, se, o);
    float lse = mx + logf(se);
    out[(long)n * F2 + lane] = x0 - lse;
    if (has2) out[(long)n * F2 + 32 + lane] = x1 - lse;
}

// ---------------- launch ----------------
extern "C" void kernel_launch(void* const* d_in, const int* in_sizes, int n_in,
                              void* d_out, int out_size) {
    const float* x   = (const float*)d_in[0];
    const int*   ei  = (const int*)d_in[1];
    const float* W1  = (const float*)d_in[2];
    const float* as1 = (const float*)d_in[3];
    const float* ad1 = (const float*)d_in[4];
    const float* b1  = (const float*)d_in[5];
    const float* W2  = (const float*)d_in[6];
    const float* as2 = (const float*)d_in[7];
    const float* ad2 = (const float*)d_in[8];
    const float* b2  = (const float*)d_in[9];
    float*       out = (float*)d_out;

    int E    = in_sizes[1] / 2;
    if (E > EMAX) E = EMAX;
    int Etot = E + NNODES;
    int nb   = (NNODES + 1023) / 1024;

    static cudaStream_t sA = nullptr, sB = nullptr;
    static cudaEvent_t  e0, eA, eB;
    if (!sA) {
        cudaStreamCreateWithFlags(&sA, cudaStreamNonBlocking);
        cudaStreamCreateWithFlags(&sB, cudaStreamNonBlocking);
        cudaEventCreateWithFlags(&e0, cudaEventDisableTiming);
        cudaEventCreateWithFlags(&eA, cudaEventDisableTiming);
        cudaEventCreateWithFlags(&eB, cudaEventDisableTiming);
        cudaFuncSetAttribute(k_gemm1_mma, cudaFuncAttributeMaxDynamicSharedMemorySize, 8 * TILEB);
    }

    cudaEventRecord(e0, 0);
    cudaStreamWaitEvent(sA, e0, 0);
    cudaStreamWaitEvent(sB, e0, 0);

    // enqueue order: launch index 3 = k_gemm1_mma (ncu window)
    k_zero_counts<<<(NNODES + 255) / 256, 256, 0, sB>>>();                    // 0
    k_count<<<(Etot + 255) / 256, 256, 0, sB>>>(ei, E, Etot);                 // 1
    k_splitB<<<(FIN * F1 + 255) / 256, 256, 0, sA>>>(W1);                     // 2
    k_gemm1_mma<<<(NNODES + 127) / 128, 256, 8 * TILEB, sA>>>(x, as1, ad1);   // 3 <- profiled
    k_scan1<<<nb, 1024, 0, sB>>>();                                           // 4
    k_scan2<<<1, 32, 0, sB>>>(nb);                                            // 5
    k_scan3<<<(NNODES + 255) / 256, 256, 0, sB>>>(Etot);                      // 6
    k_fill<<<(Etot + 255) / 256, 256, 0, sB>>>(ei, E, Etot);                  // 7

    cudaEventRecord(eA, sA);
    cudaEventRecord(eB, sB);
    cudaStreamWaitEvent(0, eA, 0);
    cudaStreamWaitEvent(0, eB, 0);

    k_agg1<<<(NNODES * 32 + 255) / 256, 256>>>(b1);                           // 8
    k_gemm2<<<(NNODES + 31) / 32, 320>>>(W2, as2, ad2);                       // 9
    k_agg2<<<(NNODES * 32 + 255) / 256, 256>>>(b2, out);                      // 10
}

// round 9
// speedup vs baseline: 1.0815x; 1.0815x over previous
#include <cuda_runtime.h>
#include <cuda_bf16.h>

#define NNODES 50000
#define FIN    512
#define H1N    8
#define C1N    16
#define F1     128      // H1*C1
#define F2     40
#define EMAX   800000
#define ETOTMAX (EMAX + NNODES)

// ---------------- static scratch ----------------
__device__ float g_h1 [NNODES * F1];
__device__ float g_h1a[NNODES * F1];
__device__ float g_as1[NNODES * H1N];
__device__ float g_ad1[NNODES * H1N];
__device__ float g_h2 [NNODES * F2];
__device__ float g_as2[NNODES];
__device__ float g_ad2[NNODES];
__device__ int   g_counts[NNODES];
__device__ int   g_rowptr[NNODES + 1];
__device__ int   g_cursor[NNODES];
__device__ int   g_csr[ETOTMAX];
__device__ int   g_bsum[64];

__device__ __nv_bfloat16 g_Bth[F1 * FIN];   // hi(W1) transposed  [n][k]
__device__ __nv_bfloat16 g_Btm[F1 * FIN];   // mid(W1) transposed [n][k]

// ---------------- CSR build ----------------
__global__ void k_zero_counts() {
    int i = blockIdx.x * blockDim.x + threadIdx.x;
    if (i < NNODES) g_counts[i] = 0;
}

__global__ void k_count(const int* __restrict__ ei, int E, int Etot) {
    int i = blockIdx.x * blockDim.x + threadIdx.x;
    if (i >= Etot) return;
    int d = (i < E) ? ei[E + i] : (i - E);
    if (d < 0 || d >= NNODES) return;
    atomicAdd(&g_counts[d], 1);
}

__global__ void k_scan1() {
    __shared__ int tmp[1024];
    int t = threadIdx.x;
    int gid = blockIdx.x * 1024 + t;
    int v = (gid < NNODES) ? g_counts[gid] : 0;
    tmp[t] = v;
    __syncthreads();
    for (int off = 1; off < 1024; off <<= 1) {
        int x = (t >= off) ? tmp[t - off] : 0;
        __syncthreads();
        tmp[t] += x;
        __syncthreads();
    }
    if (gid < NNODES) g_rowptr[gid] = tmp[t] - v;
    if (t == 1023) g_bsum[blockIdx.x] = tmp[1023];
}

__global__ void k_scan2(int nb) {
    __shared__ int sh[64];
    int t = threadIdx.x;
    int v = (t < nb) ? g_bsum[t] : 0;
    sh[t] = v;
    __syncthreads();
    for (int off = 1; off < 64; off <<= 1) {
        int x = (t >= off) ? sh[t - off] : 0;
        __syncthreads();
        sh[t] += x;
        __syncthreads();
    }
    if (t < nb) g_bsum[t] = sh[t] - v;   // exclusive
}

__global__ void k_scan3(int Etot) {
    int gid = blockIdx.x * blockDim.x + threadIdx.x;
    if (gid < NNODES) {
        int v = g_rowptr[gid] + g_bsum[gid >> 10];
        g_rowptr[gid] = v;
        g_cursor[gid] = v;
    }
    if (gid == 0) g_rowptr[NNODES] = Etot;
}

__global__ void k_fill(const int* __restrict__ ei, int E, int Etot) {
    int i = blockIdx.x * blockDim.x + threadIdx.x;
    if (i >= Etot) return;
    int s, d;
    if (i < E) { s = ei[i]; d = ei[E + i]; }
    else       { s = d = i - E; }
    if (d < 0 || d >= NNODES || s < 0 || s >= NNODES) return;
    int pos = atomicAdd(&g_cursor[d], 1);
    if (pos < ETOTMAX) g_csr[pos] = s;
}

// ---------------- bf16 split of W1 (tiny: 128KB) ----------------
__global__ void k_splitB(const float* __restrict__ W1) {
    int i = blockIdx.x * blockDim.x + threadIdx.x;
    if (i >= FIN * F1) return;
    int k = i / F1, n = i % F1;
    float v = W1[i];
    __nv_bfloat16 h = __float2bfloat16_rn(v);
    __nv_bfloat16 m = __float2bfloat16_rn(v - __bfloat162float(h));
    g_Bth[n * FIN + k] = h;
    g_Btm[n * FIN + k] = m;
}

// ---------------- GEMM1 + fused coeff1 epilogue (R6 version) ----------------
#define SWZ32(row, chk) ((row) * 64 + (((chk) ^ (((row) >> 1) & 3)) << 4))
#define TILEB 8192   // one 128x32 bf16 tile

__device__ __forceinline__ void ldmx4(unsigned* r, unsigned addr) {
    asm volatile("ldmatrix.sync.aligned.m8n8.x4.shared.b16 {%0,%1,%2,%3}, [%4];"
                 : "=r"(r[0]), "=r"(r[1]), "=r"(r[2]), "=r"(r[3]) : "r"(addr));
}

__device__ __forceinline__ void mma16816(float* c, const unsigned* a, const unsigned* b) {
    asm volatile(
        "mma.sync.aligned.m16n8k16.row.col.f32.bf16.bf16.f32 "
        "{%0,%1,%2,%3}, {%4,%5,%6,%7}, {%8,%9}, {%0,%1,%2,%3};"
        : "+f"(c[0]), "+f"(c[1]), "+f"(c[2]), "+f"(c[3])
        : "r"(a[0]), "r"(a[1]), "r"(a[2]), "r"(a[3]), "r"(b[0]), "r"(b[1]));
}

__device__ __forceinline__ void cpasync16(unsigned saddr, const void* gaddr) {
    asm volatile("cp.async.cg.shared.global [%0], [%1], 16;"
                 :: "r"(saddr), "l"(gaddr));
}

extern __shared__ __align__(16) unsigned char dynsmem[];

__global__ __launch_bounds__(256) void k_gemm1_mma(const float* __restrict__ X,
                                                   const float* __restrict__ att_s,
                                                   const float* __restrict__ att_d) {
    const int AH = 0, AM = 2 * TILEB, BH = 4 * TILEB, BMo = 6 * TILEB;
    unsigned base = (unsigned)__cvta_generic_to_shared(dynsmem);

    int tid  = threadIdx.x;
    int lane = tid & 31;
    int wid  = tid >> 5;
    int wr   = wid & 3;
    int wc   = wid >> 2;
    int bm   = blockIdx.x * 128;

    int arow = tid >> 3;
    int acol = (tid & 7) * 4;
    bool av[4];
    long gA[4];
#pragma unroll
    for (int i = 0; i < 4; i++) {
        int r = bm + arow + 32 * i;
        av[i] = r < NNODES;
        gA[i] = (long)r * FIN;
    }
    unsigned aStOff = SWZ32(arow, acol >> 3) + ((acol & 4) << 1);

    int lrow = tid >> 2, lchk = tid & 3;
    unsigned sBo0 = SWZ32(lrow, lchk), sBo1 = SWZ32(lrow + 64, lchk);

    int sub = lane >> 3, r8 = lane & 7;
    unsigned aOff[2][2], bOff[4][2];
#pragma unroll
    for (int mt = 0; mt < 2; mt++) {
        int row = wr * 32 + mt * 16 + (sub & 1) * 8 + r8;
#pragma unroll
        for (int ks = 0; ks < 2; ks++)
            aOff[mt][ks] = SWZ32(row, (sub >> 1) + 2 * ks);
    }
#pragma unroll
    for (int np = 0; np < 4; np++) {
        int row = wc * 64 + np * 16 + (sub >> 1) * 8 + r8;
#pragma unroll
        for (int ks = 0; ks < 2; ks++)
            bOff[np][ks] = SWZ32(row, (sub & 1) + 2 * ks);
    }

    float acc[2][8][4];
#pragma unroll
    for (int mt = 0; mt < 2; mt++)
#pragma unroll
        for (int nt = 0; nt < 8; nt++)
#pragma unroll
            for (int j = 0; j < 4; j++) acc[mt][nt][j] = 0.f;

    const int NIT = FIN / 32;   // 16

    auto issueB = [&](int it, int b) {
        int koff = it * 32;
        cpasync16(base + BH  + b * TILEB + sBo0, &g_Bth[(long)lrow * FIN + koff + lchk * 8]);
        cpasync16(base + BH  + b * TILEB + sBo1, &g_Bth[(long)(lrow + 64) * FIN + koff + lchk * 8]);
        cpasync16(base + BMo + b * TILEB + sBo0, &g_Btm[(long)lrow * FIN + koff + lchk * 8]);
        cpasync16(base + BMo + b * TILEB + sBo1, &g_Btm[(long)(lrow + 64) * FIN + koff + lchk * 8]);
    };
    auto loadA = [&](int it, float4* ra) {
        int koff = it * 32 + acol;
#pragma unroll
        for (int i = 0; i < 4; i++)
            ra[i] = av[i] ? *(const float4*)&X[gA[i] + koff]
                          : make_float4(0.f, 0.f, 0.f, 0.f);
    };

    float4 ra[4];
    issueB(0, 0);
    asm volatile("cp.async.commit_group;" ::);
    loadA(0, ra);

    for (int it = 0; it < NIT; it++) {
        int buf = it & 1;
#pragma unroll
        for (int i = 0; i < 4; i++) {
            float f[4] = {ra[i].x, ra[i].y, ra[i].z, ra[i].w};
            __nv_bfloat16 h[4], m[4];
#pragma unroll
            for (int j = 0; j < 4; j++) {
                h[j] = __float2bfloat16_rn(f[j]);
                m[j] = __float2bfloat16_rn(f[j] - __bfloat162float(h[j]));
            }
            unsigned off = aStOff + 32 * i * 64;
            *(uint2*)(dynsmem + AH + buf * TILEB + off) = *(uint2*)h;
            *(uint2*)(dynsmem + AM + buf * TILEB + off) = *(uint2*)m;
        }
        if (it + 1 < NIT) {
            loadA(it + 1, ra);
            issueB(it + 1, buf ^ 1);
            asm volatile("cp.async.commit_group;" ::);
            asm volatile("cp.async.wait_group 1;" ::);
        } else {
            asm volatile("cp.async.wait_group 0;" ::);
        }
        __syncthreads();

        unsigned ah = base + AH  + buf * TILEB;
        unsigned am = base + AM  + buf * TILEB;
        unsigned bh = base + BH  + buf * TILEB;
        unsigned bmm = base + BMo + buf * TILEB;
#pragma unroll
        for (int ks = 0; ks < 2; ks++) {
            unsigned bhf[4][4], bmf[4][4];
#pragma unroll
            for (int np = 0; np < 4; np++) {
                ldmx4(bhf[np], bh  + bOff[np][ks]);
                ldmx4(bmf[np], bmm + bOff[np][ks]);
            }
#pragma unroll
            for (int mt = 0; mt < 2; mt++) {
                unsigned ahf[4], amf[4];
                ldmx4(ahf, ah + aOff[mt][ks]);
                ldmx4(amf, am + aOff[mt][ks]);
#pragma unroll
                for (int nt = 0; nt < 8; nt++) {
                    const unsigned* ph = &bhf[nt >> 1][(nt & 1) * 2];
                    const unsigned* pm = &bmf[nt >> 1][(nt & 1) * 2];
                    mma16816(acc[mt][nt], ahf, ph);
                    mma16816(acc[mt][nt], amf, ph);
                    mma16816(acc[mt][nt], ahf, pm);
                }
            }
        }
        __syncthreads();
    }

    int g = lane >> 2, t = lane & 3;
#pragma unroll
    for (int mt = 0; mt < 2; mt++) {
        int r0 = bm + wr * 32 + mt * 16 + g;
        int r1 = r0 + 8;
#pragma unroll
        for (int nt = 0; nt < 8; nt++) {
            int col = wc * 64 + nt * 8 + t * 2;
            if (r0 < NNODES)
                *(float2*)&g_h1[(long)r0 * F1 + col] = make_float2(acc[mt][nt][0], acc[mt][nt][1]);
            if (r1 < NNODES)
                *(float2*)&g_h1[(long)r1 * F1 + col] = make_float2(acc[mt][nt][2], acc[mt][nt][3]);
        }
    }
    // fused coeff1
#pragma unroll
    for (int mt = 0; mt < 2; mt++) {
        int r0 = bm + wr * 32 + mt * 16 + g;
        int r1 = r0 + 8;
#pragma unroll
        for (int hh = 0; hh < 4; hh++) {
            float s0 = 0.f, d0 = 0.f, s1 = 0.f, d1 = 0.f;
#pragma unroll
            for (int q = 0; q < 2; q++) {
                int nt  = 2 * hh + q;
                int col = wc * 64 + nt * 8 + t * 2;
                float asv0 = __ldg(&att_s[col]), asv1 = __ldg(&att_s[col + 1]);
                float adv0 = __ldg(&att_d[col]), adv1 = __ldg(&att_d[col + 1]);
                s0 += acc[mt][nt][0] * asv0 + acc[mt][nt][1] * asv1;
                d0 += acc[mt][nt][0] * adv0 + acc[mt][nt][1] * adv1;
                s1 += acc[mt][nt][2] * asv0 + acc[mt][nt][3] * asv1;
                d1 += acc[mt][nt][2] * adv0 + acc[mt][nt][3] * adv1;
            }
#pragma unroll
            for (int o = 1; o <= 2; o <<= 1) {
                s0 += __shfl_xor_sync(0xFFFFFFFFu, s0, o);
                d0 += __shfl_xor_sync(0xFFFFFFFFu, d0, o);
                s1 += __shfl_xor_sync(0xFFFFFFFFu, s1, o);
                d1 += __shfl_xor_sync(0xFFFFFFFFu, d1, o);
            }
            if (t == 0) {
                int gh = wc * 4 + hh;
                if (r0 < NNODES) { g_as1[r0 * H1N + gh] = s0; g_ad1[r0 * H1N + gh] = d0; }
                if (r1 < NNODES) { g_as1[r1 * H1N + gh] = s1; g_ad1[r1 * H1N + gh] = d1; }
            }
        }
    }
}

// ---------------- layer-1 aggregation: direct-exp softmax (no running max) --
__global__ void k_agg1(const float* __restrict__ b1) {
    int gtid = blockIdx.x * blockDim.x + threadIdx.x;
    int n    = gtid >> 5;
    int lane = threadIdx.x & 31;
    if (n >= NNODES) return;
    int h = lane >> 2;
    int beg = g_rowptr[n], end = g_rowptr[n + 1];
    float adst = g_ad1[n * H1N + h];
    float s = 0.f;
    float ax = 0.f, ay = 0.f, az = 0.f, aw = 0.f;

    int   s_p2 = (beg + 1 < end) ? __ldg(&g_csr[beg + 1]) : 0;
    float e_p1 = 0.f;
    float4 v_p1 = make_float4(0.f, 0.f, 0.f, 0.f);
    if (beg < end) {
        int s0 = __ldg(&g_csr[beg]);
        e_p1 = g_as1[s0 * H1N + h];
        v_p1 = *(const float4*)&g_h1[(long)s0 * F1 + lane * 4];
    }
    for (int j = beg; j < end; j++) {
        float  e_c = e_p1 + adst;
        float4 v   = v_p1;
        int s_nxt = s_p2;
        if (j + 2 < end) s_p2 = __ldg(&g_csr[j + 2]);
        if (j + 1 < end) {
            e_p1 = g_as1[s_nxt * H1N + h];
            v_p1 = *(const float4*)&g_h1[(long)s_nxt * F1 + lane * 4];
        }
        float e = (e_c > 0.f) ? e_c : 0.2f * e_c;
        float w = __expf(fminf(e, 80.f));   // logits are O(10); shift cancels in alpha
        s  += w;
        ax += w * v.x;
        ay += w * v.y;
        az += w * v.z;
        aw += w * v.w;
    }
    float inv = 1.f / s;
    float o[4];
    o[0] = ax * inv + b1[lane * 4 + 0];
    o[1] = ay * inv + b1[lane * 4 + 1];
    o[2] = az * inv + b1[lane * 4 + 2];
    o[3] = aw * inv + b1[lane * 4 + 3];
#pragma unroll
    for (int i = 0; i < 4; i++)
        o[i] = (o[i] > 0.f) ? o[i] : (__expf(o[i]) - 1.f);
    *(float4*)&g_h1a[(long)n * F1 + lane * 4] = *(float4*)o;
}

// ---------------- GEMM2 + fused coeff2 ----------------
#define HP 132
__global__ __launch_bounds__(320) void k_gemm2(const float* __restrict__ W2,
                                               const float* __restrict__ att_s,
                                               const float* __restrict__ att_d) {
    __shared__ float hs [32 * HP];
    __shared__ float wst[40 * HP];
    __shared__ float h2s[32 * 41];
    int r0  = blockIdx.x * 32;
    int tid = threadIdx.x;
    for (int i = tid; i < 40 * F1; i += 320) {
        int c = i >> 7, k = i & 127;
        wst[c * HP + k] = W2[k * F2 + c];
    }
    for (int i = tid; i < 32 * F1; i += 320) {
        int r = i >> 7, k = i & 127;
        int gr = r0 + r;
        hs[r * HP + k] = (gr < NNODES) ? g_h1a[(long)gr * F1 + k] : 0.f;
    }
    __syncthreads();
    int c  = tid % 40;
    int rr = tid / 40;
    float acc[4] = {0.f, 0.f, 0.f, 0.f};
    for (int k4 = 0; k4 < F1 / 4; k4++) {
        float4 w = *(float4*)&wst[c * HP + k4 * 4];
#pragma unroll
        for (int i = 0; i < 4; i++) {
            float4 hv = *(float4*)&hs[(rr + i * 8) * HP + k4 * 4];
            acc[i] += w.x * hv.x + w.y * hv.y + w.z * hv.z + w.w * hv.w;
        }
    }
#pragma unroll
    for (int i = 0; i < 4; i++) {
        int r = rr + i * 8;
        int gr = r0 + r;
        h2s[r * 41 + c] = acc[i];
        if (gr < NNODES) g_h2[(long)gr * F2 + c] = acc[i];
    }
    __syncthreads();
    if (tid < 32) {
        int gr = r0 + tid;
        if (gr < NNODES) {
            float s = 0.f, d = 0.f;
#pragma unroll
            for (int cc = 0; cc < F2; cc++) {
                float v = h2s[tid * 41 + cc];
                s += v * __ldg(&att_s[cc]);
                d += v * __ldg(&att_d[cc]);
            }
            g_as2[gr] = s;
            g_ad2[gr] = d;
        }
    }
}

// ---------------- layer-2 aggregation + bias + log_softmax (direct exp) ----
__global__ void k_agg2(const float* __restrict__ b2, float* __restrict__ out) {
    int gtid = blockIdx.x * blockDim.x + threadIdx.x;
    int n    = gtid >> 5;
    int lane = threadIdx.x & 31;
    if (n >= NNODES) return;
    bool has2 = lane < 8;
    int beg = g_rowptr[n], end = g_rowptr[n + 1];
    float adst = g_ad2[n];
    float s = 0.f, a0 = 0.f, a1 = 0.f;

    int   s_p2 = (beg + 1 < end) ? __ldg(&g_csr[beg + 1]) : 0;
    float e_p1 = 0.f, v0_p = 0.f, v1_p = 0.f;
    if (beg < end) {
        int s0 = __ldg(&g_csr[beg]);
        e_p1 = g_as2[s0];
        v0_p = g_h2[(long)s0 * F2 + lane];
        v1_p = has2 ? g_h2[(long)s0 * F2 + 32 + lane] : 0.f;
    }
    for (int j = beg; j < end; j++) {
        float e_c = e_p1 + adst;
        float v0 = v0_p, v1 = v1_p;
        int s_nxt = s_p2;
        if (j + 2 < end) s_p2 = __ldg(&g_csr[j + 2]);
        if (j + 1 < end) {
            e_p1 = g_as2[s_nxt];
            v0_p = g_h2[(long)s_nxt * F2 + lane];
            v1_p = has2 ? g_h2[(long)s_nxt * F2 + 32 + lane] : 0.f;
        }
        float e = (e_c > 0.f) ? e_c : 0.2f * e_c;
        float w = __expf(fminf(e, 80.f));
        s  += w;
        a0 += w * v0;
        a1 += w * v1;
    }
    float inv = 1.f / s;
    float x0 = a0 * inv + b2[lane];
    float x1 = has2 ? (a1 * inv + b2[32 + lane]) : -1e30f;
    float mx = fmaxf(x0, x1);
#pragma unroll
    for (int o = 16; o; o >>= 1) mx = fmaxf(mx, __shfl_xor_sync(0xFFFFFFFFu, mx, o));
    float se = __expf(x0 - mx) + (has2 ? __expf(x1 - mx) : 0.f);
#pragma unroll
    for (int o = 16; o; o >>= 1) se += __shfl_xor_sync(0xFFFFFFFFu, se, o);
    float lse = mx + logf(se);
    out[(long)n * F2 + lane] = x0 - lse;
    if (has2) out[(long)n * F2 + 32 + lane] = x1 - lse;
}

// ---------------- launch ----------------
extern "C" void kernel_launch(void* const* d_in, const int* in_sizes, int n_in,
                              void* d_out, int out_size) {
    const float* x   = (const float*)d_in[0];
    const int*   ei  = (const int*)d_in[1];
    const float* W1  = (const float*)d_in[2];
    const float* as1 = (const float*)d_in[3];
    const float* ad1 = (const float*)d_in[4];
    const float* b1  = (const float*)d_in[5];
    const float* W2  = (const float*)d_in[6];
    const float* as2 = (const float*)d_in[7];
    const float* ad2 = (const float*)d_in[8];
    const float* b2  = (const float*)d_in[9];
    float*       out = (float*)d_out;

    int E    = in_sizes[1] / 2;
    if (E > EMAX) E = EMAX;
    int Etot = E + NNODES;
    int nb   = (NNODES + 1023) / 1024;

    static cudaStream_t sA = nullptr, sB = nullptr;
    static cudaEvent_t  e0, eA, eB;
    if (!sA) {
        cudaStreamCreateWithFlags(&sA, cudaStreamNonBlocking);
        cudaStreamCreateWithFlags(&sB, cudaStreamNonBlocking);
        cudaEventCreateWithFlags(&e0, cudaEventDisableTiming);
        cudaEventCreateWithFlags(&eA, cudaEventDisableTiming);
        cudaEventCreateWithFlags(&eB, cudaEventDisableTiming);
        cudaFuncSetAttribute(k_gemm1_mma, cudaFuncAttributeMaxDynamicSharedMemorySize, 8 * TILEB);
    }

    cudaEventRecord(e0, 0);
    cudaStreamWaitEvent(sA, e0, 0);
    cudaStreamWaitEvent(sB, e0, 0);

    // enqueue order: launch index 3 = k_gemm1_mma (ncu window)
    k_zero_counts<<<(NNODES + 255) / 256, 256, 0, sB>>>();                    // 0
    k_count<<<(Etot + 255) / 256, 256, 0, sB>>>(ei, E, Etot);                 // 1
    k_splitB<<<(FIN * F1 + 255) / 256, 256, 0, sA>>>(W1);                     // 2
    k_gemm1_mma<<<(NNODES + 127) / 128, 256, 8 * TILEB, sA>>>(x, as1, ad1);   // 3 <- profiled
    k_scan1<<<nb, 1024, 0, sB>>>();                                           // 4
    k_scan2<<<1, 64, 0, sB>>>(nb);                                            // 5
    k_scan3<<<(NNODES + 255) / 256, 256, 0, sB>>>(Etot);                      // 6
    k_fill<<<(Etot + 255) / 256, 256, 0, sB>>>(ei, E, Etot);                  // 7

    cudaEventRecord(eA, sA);
    cudaEventRecord(eB, sB);
    cudaStreamWaitEvent(0, eA, 0);
    cudaStreamWaitEvent(0, eB, 0);

    k_agg1<<<(NNODES * 32 + 255) / 256, 256>>>(b1);                           // 8
    k_gemm2<<<(NNODES + 31) / 32, 320>>>(W2, as2, ad2);                       // 9
    k_agg2<<<(NNODES * 32 + 255) / 256, 256>>>(b2, out);                      // 10
}

// round 10
// speedup vs baseline: 1.1554x; 1.0684x over previous
#include <cuda_runtime.h>
#include <cuda_bf16.h>

#define NNODES 50000
#define FIN    512
#define H1N    8
#define C1N    16
#define F1     128      // H1*C1
#define F2     40
#define EMAX   800000
#define ETOTMAX (EMAX + NNODES)
#define NH0    25024    // lo/hi node split (64-aligned)

// ---------------- static scratch ----------------
__device__ float g_h1 [NNODES * F1];
__device__ float g_h1a[NNODES * F1];
__device__ float g_as1[NNODES * H1N];
__device__ float g_ad1[NNODES * H1N];
__device__ float g_h2 [NNODES * F2];
__device__ float g_as2[NNODES];
__device__ float g_ad2[NNODES];
__device__ int   g_counts[NNODES];
__device__ int   g_rowptr[NNODES + 1];
__device__ int   g_cursor[NNODES];
__device__ int   g_csr[ETOTMAX];
__device__ int   g_bsum[64];

__device__ __nv_bfloat16 g_Bth[F1 * FIN];   // hi(W1) transposed  [n][k]
__device__ __nv_bfloat16 g_Btm[F1 * FIN];   // mid(W1) transposed [n][k]

// ---------------- CSR build ----------------
__global__ void k_zero_counts() {
    int i = blockIdx.x * blockDim.x + threadIdx.x;
    if (i < NNODES) g_counts[i] = 0;
}

__global__ void k_count(const int* __restrict__ ei, int E, int Etot) {
    int i = blockIdx.x * blockDim.x + threadIdx.x;
    if (i >= Etot) return;
    int d = (i < E) ? ei[E + i] : (i - E);
    if (d < 0 || d >= NNODES) return;
    atomicAdd(&g_counts[d], 1);
}

__global__ void k_scan1() {
    __shared__ int tmp[1024];
    int t = threadIdx.x;
    int gid = blockIdx.x * 1024 + t;
    int v = (gid < NNODES) ? g_counts[gid] : 0;
    tmp[t] = v;
    __syncthreads();
    for (int off = 1; off < 1024; off <<= 1) {
        int x = (t >= off) ? tmp[t - off] : 0;
        __syncthreads();
        tmp[t] += x;
        __syncthreads();
    }
    if (gid < NNODES) g_rowptr[gid] = tmp[t] - v;
    if (t == 1023) g_bsum[blockIdx.x] = tmp[1023];
}

__global__ void k_scan2(int nb) {
    __shared__ int sh[64];
    int t = threadIdx.x;
    int v = (t < nb) ? g_bsum[t] : 0;
    sh[t] = v;
    __syncthreads();
    for (int off = 1; off < 64; off <<= 1) {
        int x = (t >= off) ? sh[t - off] : 0;
        __syncthreads();
        sh[t] += x;
        __syncthreads();
    }
    if (t < nb) g_bsum[t] = sh[t] - v;   // exclusive
}

__global__ void k_scan3(int Etot) {
    int gid = blockIdx.x * blockDim.x + threadIdx.x;
    if (gid < NNODES) {
        int v = g_rowptr[gid] + g_bsum[gid >> 10];
        g_rowptr[gid] = v;
        g_cursor[gid] = v;
    }
    if (gid == 0) g_rowptr[NNODES] = Etot;
}

__global__ void k_fill(const int* __restrict__ ei, int E, int Etot) {
    int i = blockIdx.x * blockDim.x + threadIdx.x;
    if (i >= Etot) return;
    int s, d;
    if (i < E) { s = ei[i]; d = ei[E + i]; }
    else       { s = d = i - E; }
    if (d < 0 || d >= NNODES || s < 0 || s >= NNODES) return;
    int pos = atomicAdd(&g_cursor[d], 1);
    if (pos < ETOTMAX) g_csr[pos] = s;
}

// ---------------- bf16 split of W1 (tiny: 128KB) ----------------
__global__ void k_splitB(const float* __restrict__ W1) {
    int i = blockIdx.x * blockDim.x + threadIdx.x;
    if (i >= FIN * F1) return;
    int k = i / F1, n = i % F1;
    float v = W1[i];
    __nv_bfloat16 h = __float2bfloat16_rn(v);
    __nv_bfloat16 m = __float2bfloat16_rn(v - __bfloat162float(h));
    g_Bth[n * FIN + k] = h;
    g_Btm[n * FIN + k] = m;
}

// ---------------- GEMM1 + fused coeff1 epilogue ----------------
#define SWZ32(row, chk) ((row) * 64 + (((chk) ^ (((row) >> 1) & 3)) << 4))
#define TILEB 8192   // one 128x32 bf16 tile

__device__ __forceinline__ void ldmx4(unsigned* r, unsigned addr) {
    asm volatile("ldmatrix.sync.aligned.m8n8.x4.shared.b16 {%0,%1,%2,%3}, [%4];"
                 : "=r"(r[0]), "=r"(r[1]), "=r"(r[2]), "=r"(r[3]) : "r"(addr));
}

__device__ __forceinline__ void mma16816(float* c, const unsigned* a, const unsigned* b) {
    asm volatile(
        "mma.sync.aligned.m16n8k16.row.col.f32.bf16.bf16.f32 "
        "{%0,%1,%2,%3}, {%4,%5,%6,%7}, {%8,%9}, {%0,%1,%2,%3};"
        : "+f"(c[0]), "+f"(c[1]), "+f"(c[2]), "+f"(c[3])
        : "r"(a[0]), "r"(a[1]), "r"(a[2]), "r"(a[3]), "r"(b[0]), "r"(b[1]));
}

__device__ __forceinline__ void cpasync16(unsigned saddr, const void* gaddr) {
    asm volatile("cp.async.cg.shared.global [%0], [%1], 16;"
                 :: "r"(saddr), "l"(gaddr));
}

extern __shared__ __align__(16) unsigned char dynsmem[];

__global__ __launch_bounds__(256) void k_gemm1_mma(const float* __restrict__ X,
                                                   const float* __restrict__ att_s,
                                                   const float* __restrict__ att_d) {
    const int AH = 0, AM = 2 * TILEB, BH = 4 * TILEB, BMo = 6 * TILEB;
    unsigned base = (unsigned)__cvta_generic_to_shared(dynsmem);

    int tid  = threadIdx.x;
    int lane = tid & 31;
    int wid  = tid >> 5;
    int wr   = wid & 3;
    int wc   = wid >> 2;
    int bm   = blockIdx.x * 128;

    int arow = tid >> 3;
    int acol = (tid & 7) * 4;
    bool av[4];
    long gA[4];
#pragma unroll
    for (int i = 0; i < 4; i++) {
        int r = bm + arow + 32 * i;
        av[i] = r < NNODES;
        gA[i] = (long)r * FIN;
    }
    unsigned aStOff = SWZ32(arow, acol >> 3) + ((acol & 4) << 1);

    int lrow = tid >> 2, lchk = tid & 3;
    unsigned sBo0 = SWZ32(lrow, lchk), sBo1 = SWZ32(lrow + 64, lchk);

    int sub = lane >> 3, r8 = lane & 7;
    unsigned aOff[2][2], bOff[4][2];
#pragma unroll
    for (int mt = 0; mt < 2; mt++) {
        int row = wr * 32 + mt * 16 + (sub & 1) * 8 + r8;
#pragma unroll
        for (int ks = 0; ks < 2; ks++)
            aOff[mt][ks] = SWZ32(row, (sub >> 1) + 2 * ks);
    }
#pragma unroll
    for (int np = 0; np < 4; np++) {
        int row = wc * 64 + np * 16 + (sub >> 1) * 8 + r8;
#pragma unroll
        for (int ks = 0; ks < 2; ks++)
            bOff[np][ks] = SWZ32(row, (sub & 1) + 2 * ks);
    }

    float acc[2][8][4];
#pragma unroll
    for (int mt = 0; mt < 2; mt++)
#pragma unroll
        for (int nt = 0; nt < 8; nt++)
#pragma unroll
            for (int j = 0; j < 4; j++) acc[mt][nt][j] = 0.f;

    const int NIT = FIN / 32;   // 16

    auto issueB = [&](int it, int b) {
        int koff = it * 32;
        cpasync16(base + BH  + b * TILEB + sBo0, &g_Bth[(long)lrow * FIN + koff + lchk * 8]);
        cpasync16(base + BH  + b * TILEB + sBo1, &g_Bth[(long)(lrow + 64) * FIN + koff + lchk * 8]);
        cpasync16(base + BMo + b * TILEB + sBo0, &g_Btm[(long)lrow * FIN + koff + lchk * 8]);
        cpasync16(base + BMo + b * TILEB + sBo1, &g_Btm[(long)(lrow + 64) * FIN + koff + lchk * 8]);
    };
    auto loadA = [&](int it, float4* ra) {
        int koff = it * 32 + acol;
#pragma unroll
        for (int i = 0; i < 4; i++)
            ra[i] = av[i] ? *(const float4*)&X[gA[i] + koff]
                          : make_float4(0.f, 0.f, 0.f, 0.f);
    };

    float4 ra[4];
    issueB(0, 0);
    asm volatile("cp.async.commit_group;" ::);
    loadA(0, ra);

    for (int it = 0; it < NIT; it++) {
        int buf = it & 1;
#pragma unroll
        for (int i = 0; i < 4; i++) {
            float f[4] = {ra[i].x, ra[i].y, ra[i].z, ra[i].w};
            __nv_bfloat16 h[4], m[4];
#pragma unroll
            for (int j = 0; j < 4; j++) {
                h[j] = __float2bfloat16_rn(f[j]);
                m[j] = __float2bfloat16_rn(f[j] - __bfloat162float(h[j]));
            }
            unsigned off = aStOff + 32 * i * 64;
            *(uint2*)(dynsmem + AH + buf * TILEB + off) = *(uint2*)h;
            *(uint2*)(dynsmem + AM + buf * TILEB + off) = *(uint2*)m;
        }
        if (it + 1 < NIT) {
            loadA(it + 1, ra);
            issueB(it + 1, buf ^ 1);
            asm volatile("cp.async.commit_group;" ::);
            asm volatile("cp.async.wait_group 1;" ::);
        } else {
            asm volatile("cp.async.wait_group 0;" ::);
        }
        __syncthreads();

        unsigned ah = base + AH  + buf * TILEB;
        unsigned am = base + AM  + buf * TILEB;
        unsigned bh = base + BH  + buf * TILEB;
        unsigned bmm = base + BMo + buf * TILEB;
#pragma unroll
        for (int ks = 0; ks < 2; ks++) {
            unsigned bhf[4][4], bmf[4][4];
#pragma unroll
            for (int np = 0; np < 4; np++) {
                ldmx4(bhf[np], bh  + bOff[np][ks]);
                ldmx4(bmf[np], bmm + bOff[np][ks]);
            }
#pragma unroll
            for (int mt = 0; mt < 2; mt++) {
                unsigned ahf[4], amf[4];
                ldmx4(ahf, ah + aOff[mt][ks]);
                ldmx4(amf, am + aOff[mt][ks]);
#pragma unroll
                for (int nt = 0; nt < 8; nt++) {
                    const unsigned* ph = &bhf[nt >> 1][(nt & 1) * 2];
                    const unsigned* pm = &bmf[nt >> 1][(nt & 1) * 2];
                    mma16816(acc[mt][nt], ahf, ph);
                    mma16816(acc[mt][nt], amf, ph);
                    mma16816(acc[mt][nt], ahf, pm);
                }
            }
        }
        __syncthreads();
    }

    int g = lane >> 2, t = lane & 3;
#pragma unroll
    for (int mt = 0; mt < 2; mt++) {
        int r0 = bm + wr * 32 + mt * 16 + g;
        int r1 = r0 + 8;
#pragma unroll
        for (int nt = 0; nt < 8; nt++) {
            int col = wc * 64 + nt * 8 + t * 2;
            if (r0 < NNODES)
                *(float2*)&g_h1[(long)r0 * F1 + col] = make_float2(acc[mt][nt][0], acc[mt][nt][1]);
            if (r1 < NNODES)
                *(float2*)&g_h1[(long)r1 * F1 + col] = make_float2(acc[mt][nt][2], acc[mt][nt][3]);
        }
    }
    // fused coeff1
#pragma unroll
    for (int mt = 0; mt < 2; mt++) {
        int r0 = bm + wr * 32 + mt * 16 + g;
        int r1 = r0 + 8;
#pragma unroll
        for (int hh = 0; hh < 4; hh++) {
            float s0 = 0.f, d0 = 0.f, s1 = 0.f, d1 = 0.f;
#pragma unroll
            for (int q = 0; q < 2; q++) {
                int nt  = 2 * hh + q;
                int col = wc * 64 + nt * 8 + t * 2;
                float asv0 = __ldg(&att_s[col]), asv1 = __ldg(&att_s[col + 1]);
                float adv0 = __ldg(&att_d[col]), adv1 = __ldg(&att_d[col + 1]);
                s0 += acc[mt][nt][0] * asv0 + acc[mt][nt][1] * asv1;
                d0 += acc[mt][nt][0] * adv0 + acc[mt][nt][1] * adv1;
                s1 += acc[mt][nt][2] * asv0 + acc[mt][nt][3] * asv1;
                d1 += acc[mt][nt][2] * adv0 + acc[mt][nt][3] * adv1;
            }
#pragma unroll
            for (int o = 1; o <= 2; o <<= 1) {
                s0 += __shfl_xor_sync(0xFFFFFFFFu, s0, o);
                d0 += __shfl_xor_sync(0xFFFFFFFFu, d0, o);
                s1 += __shfl_xor_sync(0xFFFFFFFFu, s1, o);
                d1 += __shfl_xor_sync(0xFFFFFFFFu, d1, o);
            }
            if (t == 0) {
                int gh = wc * 4 + hh;
                if (r0 < NNODES) { g_as1[r0 * H1N + gh] = s0; g_ad1[r0 * H1N + gh] = d0; }
                if (r1 < NNODES) { g_as1[r1 * H1N + gh] = s1; g_ad1[r1 * H1N + gh] = d1; }
            }
        }
    }
}

// ---------------- layer-1 aggregation: direct-exp softmax, node range ------
__global__ void k_agg1(const float* __restrict__ b1, int n0, int n1) {
    int gtid = blockIdx.x * blockDim.x + threadIdx.x;
    int n    = n0 + (gtid >> 5);
    int lane = threadIdx.x & 31;
    if (n >= n1) return;
    int h = lane >> 2;
    int beg = g_rowptr[n], end = g_rowptr[n + 1];
    float adst = g_ad1[n * H1N + h];
    float s = 0.f;
    float ax = 0.f, ay = 0.f, az = 0.f, aw = 0.f;

    int   s_p2 = (beg + 1 < end) ? __ldg(&g_csr[beg + 1]) : 0;
    float e_p1 = 0.f;
    float4 v_p1 = make_float4(0.f, 0.f, 0.f, 0.f);
    if (beg < end) {
        int s0 = __ldg(&g_csr[beg]);
        e_p1 = g_as1[s0 * H1N + h];
        v_p1 = *(const float4*)&g_h1[(long)s0 * F1 + lane * 4];
    }
    for (int j = beg; j < end; j++) {
        float  e_c = e_p1 + adst;
        float4 v   = v_p1;
        int s_nxt = s_p2;
        if (j + 2 < end) s_p2 = __ldg(&g_csr[j + 2]);
        if (j + 1 < end) {
            e_p1 = g_as1[s_nxt * H1N + h];
            v_p1 = *(const float4*)&g_h1[(long)s_nxt * F1 + lane * 4];
        }
        float e = (e_c > 0.f) ? e_c : 0.2f * e_c;
        float w = __expf(fminf(e, 80.f));
        s  += w;
        ax += w * v.x;
        ay += w * v.y;
        az += w * v.z;
        aw += w * v.w;
    }
    float inv = 1.f / s;
    float o[4];
    o[0] = ax * inv + b1[lane * 4 + 0];
    o[1] = ay * inv + b1[lane * 4 + 1];
    o[2] = az * inv + b1[lane * 4 + 2];
    o[3] = aw * inv + b1[lane * 4 + 3];
#pragma unroll
    for (int i = 0; i < 4; i++)
        o[i] = (o[i] > 0.f) ? o[i] : (__expf(o[i]) - 1.f);
    *(float4*)&g_h1a[(long)n * F1 + lane * 4] = *(float4*)o;
}

// ---------------- GEMM2 + fused coeff2 (4x5 thread tile, 64-row blocks) ----
// smem floats: hs[64*132] + wst[40*132] + h2s[64*41]
#define GS2_BYTES ((64 * 132 + 40 * 132 + 64 * 41) * 4)
__global__ __launch_bounds__(128) void k_gemm2(const float* __restrict__ W2,
                                               const float* __restrict__ att_s,
                                               const float* __restrict__ att_d,
                                               int n0, int n1) {
    float* hs  = (float*)dynsmem;        // [64][132]
    float* wst = hs + 64 * 132;          // [40][132]  W2 transposed
    float* h2s = wst + 40 * 132;         // [64][41]
    int r0  = n0 + blockIdx.x * 64;
    int tid = threadIdx.x;

    // W2 transposed into smem (coalesced global reads)
    for (int i = tid; i < F2 * F1; i += 128) {
        int k = i / F2, c = i - k * F2;
        wst[c * 132 + k] = W2[i];
    }
    // h1a rows (float4, coalesced)
    for (int i = tid; i < 64 * 32; i += 128) {
        int r = i >> 5, k4 = i & 31;
        int gr = r0 + r;
        float4 v = (gr < n1) ? *(const float4*)&g_h1a[(long)gr * F1 + k4 * 4]
                             : make_float4(0.f, 0.f, 0.f, 0.f);
        *(float4*)&hs[r * 132 + k4 * 4] = v;
    }
    __syncthreads();

    int rowg = tid >> 3;   // 0..15 -> rows rowg + 16i
    int colg = tid & 7;    // 0..7  -> cols colg*5 .. +4
    float acc[4][5];
#pragma unroll
    for (int i = 0; i < 4; i++)
#pragma unroll
        for (int j = 0; j < 5; j++) acc[i][j] = 0.f;

    for (int k4 = 0; k4 < 32; k4++) {
        float4 w[5];
#pragma unroll
        for (int j = 0; j < 5; j++)
            w[j] = *(float4*)&wst[(colg * 5 + j) * 132 + k4 * 4];
#pragma unroll
        for (int i = 0; i < 4; i++) {
            float4 hv = *(float4*)&hs[(rowg + 16 * i) * 132 + k4 * 4];
#pragma unroll
            for (int j = 0; j < 5; j++)
                acc[i][j] += hv.x * w[j].x + hv.y * w[j].y + hv.z * w[j].z + hv.w * w[j].w;
        }
    }
#pragma unroll
    for (int i = 0; i < 4; i++) {
        int r = rowg + 16 * i;
#pragma unroll
        for (int j = 0; j < 5; j++)
            h2s[r * 41 + colg * 5 + j] = acc[i][j];
    }
    __syncthreads();
    // coalesced h2 writeback
    for (int i = tid; i < 64 * F2; i += 128) {
        int r = i / F2, c = i - r * F2;
        int gr = r0 + r;
        if (gr < n1) g_h2[(long)gr * F2 + c] = h2s[r * 41 + c];
    }
    // fused coeff2
    if (tid < 64) {
        int gr = r0 + tid;
        if (gr < n1) {
            float s = 0.f, d = 0.f;
#pragma unroll
            for (int cc = 0; cc < F2; cc++) {
                float v = h2s[tid * 41 + cc];
                s += v * __ldg(&att_s[cc]);
                d += v * __ldg(&att_d[cc]);
            }
            g_as2[gr] = s;
            g_ad2[gr] = d;
        }
    }
}

// ---------------- layer-2 aggregation + bias + log_softmax (direct exp) ----
__global__ void k_agg2(const float* __restrict__ b2, float* __restrict__ out) {
    int gtid = blockIdx.x * blockDim.x + threadIdx.x;
    int n    = gtid >> 5;
    int lane = threadIdx.x & 31;
    if (n >= NNODES) return;
    bool has2 = lane < 8;
    int beg = g_rowptr[n], end = g_rowptr[n + 1];
    float adst = g_ad2[n];
    float s = 0.f, a0 = 0.f, a1 = 0.f;

    int   s_p2 = (beg + 1 < end) ? __ldg(&g_csr[beg + 1]) : 0;
    float e_p1 = 0.f, v0_p = 0.f, v1_p = 0.f;
    if (beg < end) {
        int s0 = __ldg(&g_csr[beg]);
        e_p1 = g_as2[s0];
        v0_p = g_h2[(long)s0 * F2 + lane];
        v1_p = has2 ? g_h2[(long)s0 * F2 + 32 + lane] : 0.f;
    }
    for (int j = beg; j < end; j++) {
        float e_c = e_p1 + adst;
        float v0 = v0_p, v1 = v1_p;
        int s_nxt = s_p2;
        if (j + 2 < end) s_p2 = __ldg(&g_csr[j + 2]);
        if (j + 1 < end) {
            e_p1 = g_as2[s_nxt];
            v0_p = g_h2[(long)s_nxt * F2 + lane];
            v1_p = has2 ? g_h2[(long)s_nxt * F2 + 32 + lane] : 0.f;
        }
        float e = (e_c > 0.f) ? e_c : 0.2f * e_c;
        float w = __expf(fminf(e, 80.f));
        s  += w;
        a0 += w * v0;
        a1 += w * v1;
    }
    float inv = 1.f / s;
    float x0 = a0 * inv + b2[lane];
    float x1 = has2 ? (a1 * inv + b2[32 + lane]) : -1e30f;
    float mx = fmaxf(x0, x1);
#pragma unroll
    for (int o = 16; o; o >>= 1) mx = fmaxf(mx, __shfl_xor_sync(0xFFFFFFFFu, mx, o));
    float se = __expf(x0 - mx) + (has2 ? __expf(x1 - mx) : 0.f);
#pragma unroll
    for (int o = 16; o; o >>= 1) se += __shfl_xor_sync(0xFFFFFFFFu, se, o);
    float lse = mx + logf(se);
    out[(long)n * F2 + lane] = x0 - lse;
    if (has2) out[(long)n * F2 + 32 + lane] = x1 - lse;
}

// ---------------- launch ----------------
extern "C" void kernel_launch(void* const* d_in, const int* in_sizes, int n_in,
                              void* d_out, int out_size) {
    const float* x   = (const float*)d_in[0];
    const int*   ei  = (const int*)d_in[1];
    const float* W1  = (const float*)d_in[2];
    const float* as1 = (const float*)d_in[3];
    const float* ad1 = (const float*)d_in[4];
    const float* b1  = (const float*)d_in[5];
    const float* W2  = (const float*)d_in[6];
    const float* as2 = (const float*)d_in[7];
    const float* ad2 = (const float*)d_in[8];
    const float* b2  = (const float*)d_in[9];
    float*       out = (float*)d_out;

    int E    = in_sizes[1] / 2;
    if (E > EMAX) E = EMAX;
    int Etot = E + NNODES;
    int nb   = (NNODES + 1023) / 1024;

    static cudaStream_t sA = nullptr, sB = nullptr;
    static cudaEvent_t  e0, eA1, eB, eA2;
    if (!sA) {
        cudaStreamCreateWithFlags(&sA, cudaStreamNonBlocking);
        cudaStreamCreateWithFlags(&sB, cudaStreamNonBlocking);
        cudaEventCreateWithFlags(&e0,  cudaEventDisableTiming);
        cudaEventCreateWithFlags(&eA1, cudaEventDisableTiming);
        cudaEventCreateWithFlags(&eB,  cudaEventDisableTiming);
        cudaEventCreateWithFlags(&eA2, cudaEventDisableTiming);
        cudaFuncSetAttribute(k_gemm1_mma, cudaFuncAttributeMaxDynamicSharedMemorySize, 8 * TILEB);
        cudaFuncSetAttribute(k_gemm2, cudaFuncAttributeMaxDynamicSharedMemorySize, GS2_BYTES);
    }

    cudaEventRecord(e0, 0);
    cudaStreamWaitEvent(sA, e0, 0);
    cudaStreamWaitEvent(sB, e0, 0);

    const int NLO = NH0;              // 25024 nodes (391 x 64)
    const int NHI = NNODES - NH0;     // 24976 nodes

    // enqueue order: launch index 3 = k_gemm1_mma (ncu window)
    k_zero_counts<<<(NNODES + 255) / 256, 256, 0, sB>>>();                    // 0
    k_count<<<(Etot + 255) / 256, 256, 0, sB>>>(ei, E, Etot);                 // 1
    k_splitB<<<(FIN * F1 + 255) / 256, 256, 0, sA>>>(W1);                     // 2
    k_gemm1_mma<<<(NNODES + 127) / 128, 256, 8 * TILEB, sA>>>(x, as1, ad1);   // 3 <- profiled
    cudaEventRecord(eA1, sA);
    k_scan1<<<nb, 1024, 0, sB>>>();                                           // 4
    k_scan2<<<1, 64, 0, sB>>>(nb);                                            // 5
    k_scan3<<<(NNODES + 255) / 256, 256, 0, sB>>>(Etot);                      // 6
    k_fill<<<(Etot + 255) / 256, 256, 0, sB>>>(ei, E, Etot);                  // 7
    cudaEventRecord(eB, sB);

    // stream A: hi-half aggregation + gemm2 (gemm1 already ordered in-stream)
    cudaStreamWaitEvent(sA, eB, 0);
    k_agg1<<<(NHI * 32 + 255) / 256, 256, 0, sA>>>(b1, NH0, NNODES);          // 8
    k_gemm2<<<(NHI + 63) / 64, 128, GS2_BYTES, sA>>>(W2, as2, ad2, NH0, NNODES); // 9
    cudaEventRecord(eA2, sA);

    // default stream: lo-half aggregation + gemm2, then final agg2
    cudaStreamWaitEvent(0, eA1, 0);
    cudaStreamWaitEvent(0, eB, 0);
    k_agg1<<<(NLO * 32 + 255) / 256, 256>>>(b1, 0, NH0);                      // 10
    k_gemm2<<<(NLO + 63) / 64, 128, GS2_BYTES>>>(W2, as2, ad2, 0, NH0);       // 11
    cudaStreamWaitEvent(0, eA2, 0);
    k_agg2<<<(NNODES * 32 + 255) / 256, 256>>>(b2, out);                      // 12
}

// round 11
// speedup vs baseline: 1.2010x; 1.0394x over previous
#include <cuda_runtime.h>
#include <cuda_fp16.h>

#define NNODES 50000
#define FIN    512
#define H1N    8
#define C1N    16
#define F1     128      // H1*C1
#define F2     40
#define EMAX   800000
#define ETOTMAX (EMAX + NNODES)
#define NH0    25024    // lo/hi node split (64-aligned)

// ---------------- static scratch ----------------
__device__ float g_h1 [NNODES * F1];
__device__ float g_h1a[NNODES * F1];
__device__ float g_as1[NNODES * H1N];
__device__ float g_ad1[NNODES * H1N];
__device__ float g_h2 [NNODES * F2];
__device__ float g_as2[NNODES];
__device__ float g_ad2[NNODES];
__device__ int   g_counts[NNODES];
__device__ int   g_rowptr[NNODES + 1];
__device__ int   g_cursor[NNODES];
__device__ int   g_csr[ETOTMAX];
__device__ int   g_bsum[64];

__device__ __half g_Bth[F1 * FIN];   // hi(W1)  fp16, transposed [n][k]
__device__ __half g_Btm[F1 * FIN];   // mid(W1) fp16, transposed [n][k]

// ---------------- CSR build ----------------
__global__ void k_zero_counts() {
    int i = blockIdx.x * blockDim.x + threadIdx.x;
    if (i < NNODES) g_counts[i] = 0;
}

__global__ void k_count(const int* __restrict__ ei, int E, int Etot) {
    int i = blockIdx.x * blockDim.x + threadIdx.x;
    if (i >= Etot) return;
    int d = (i < E) ? ei[E + i] : (i - E);
    if (d < 0 || d >= NNODES) return;
    atomicAdd(&g_counts[d], 1);
}

__global__ void k_scan1() {
    __shared__ int tmp[1024];
    int t = threadIdx.x;
    int gid = blockIdx.x * 1024 + t;
    int v = (gid < NNODES) ? g_counts[gid] : 0;
    tmp[t] = v;
    __syncthreads();
    for (int off = 1; off < 1024; off <<= 1) {
        int x = (t >= off) ? tmp[t - off] : 0;
        __syncthreads();
        tmp[t] += x;
        __syncthreads();
    }
    if (gid < NNODES) g_rowptr[gid] = tmp[t] - v;
    if (t == 1023) g_bsum[blockIdx.x] = tmp[1023];
}

__global__ void k_scan2(int nb) {
    __shared__ int sh[64];
    int t = threadIdx.x;
    int v = (t < nb) ? g_bsum[t] : 0;
    sh[t] = v;
    __syncthreads();
    for (int off = 1; off < 64; off <<= 1) {
        int x = (t >= off) ? sh[t - off] : 0;
        __syncthreads();
        sh[t] += x;
        __syncthreads();
    }
    if (t < nb) g_bsum[t] = sh[t] - v;   // exclusive
}

__global__ void k_scan3(int Etot) {
    int gid = blockIdx.x * blockDim.x + threadIdx.x;
    if (gid < NNODES) {
        int v = g_rowptr[gid] + g_bsum[gid >> 10];
        g_rowptr[gid] = v;
        g_cursor[gid] = v;
    }
    if (gid == 0) g_rowptr[NNODES] = Etot;
}

__global__ void k_fill(const int* __restrict__ ei, int E, int Etot) {
    int i = blockIdx.x * blockDim.x + threadIdx.x;
    if (i >= Etot) return;
    int s, d;
    if (i < E) { s = ei[i]; d = ei[E + i]; }
    else       { s = d = i - E; }
    if (d < 0 || d >= NNODES || s < 0 || s >= NNODES) return;
    int pos = atomicAdd(&g_cursor[d], 1);
    if (pos < ETOTMAX) g_csr[pos] = s;
}

// ---------------- fp16 hi/mid split of W1 (tiny: 128KB) ----------------
__global__ void k_splitB(const float* __restrict__ W1) {
    int i = blockIdx.x * blockDim.x + threadIdx.x;
    if (i >= FIN * F1) return;
    int k = i / F1, n = i % F1;
    float v = W1[i];
    __half h = __float2half_rn(v);
    __half m = __float2half_rn(v - __half2float(h));
    g_Bth[n * FIN + k] = h;
    g_Btm[n * FIN + k] = m;
}

// ---------------- GEMM1 + fused coeff1 epilogue ----------------
// h1 = x@W1 via A_fp16*(Bh + Bm): A single fp16, B split fp16 hi/mid.
#define SWZ32(row, chk) ((row) * 64 + (((chk) ^ (((row) >> 1) & 3)) << 4))
#define TILEB 8192   // one 128x32 fp16 tile

__device__ __forceinline__ void ldmx4(unsigned* r, unsigned addr) {
    asm volatile("ldmatrix.sync.aligned.m8n8.x4.shared.b16 {%0,%1,%2,%3}, [%4];"
                 : "=r"(r[0]), "=r"(r[1]), "=r"(r[2]), "=r"(r[3]) : "r"(addr));
}

__device__ __forceinline__ void mma16816h(float* c, const unsigned* a, const unsigned* b) {
    asm volatile(
        "mma.sync.aligned.m16n8k16.row.col.f32.f16.f16.f32 "
        "{%0,%1,%2,%3}, {%4,%5,%6,%7}, {%8,%9}, {%0,%1,%2,%3};"
        : "+f"(c[0]), "+f"(c[1]), "+f"(c[2]), "+f"(c[3])
        : "r"(a[0]), "r"(a[1]), "r"(a[2]), "r"(a[3]), "r"(b[0]), "r"(b[1]));
}

__device__ __forceinline__ void cpasync16(unsigned saddr, const void* gaddr) {
    asm volatile("cp.async.cg.shared.global [%0], [%1], 16;"
                 :: "r"(saddr), "l"(gaddr));
}

extern __shared__ __align__(16) unsigned char dynsmem[];

__global__ __launch_bounds__(256) void k_gemm1_mma(const float* __restrict__ X,
                                                   const float* __restrict__ att_s,
                                                   const float* __restrict__ att_d) {
    // smem regions (double buffered): AH [0,2T), BH [2T,4T), BM [4T,6T)
    const int AH = 0, BH = 2 * TILEB, BMo = 4 * TILEB;
    unsigned base = (unsigned)__cvta_generic_to_shared(dynsmem);

    int tid  = threadIdx.x;
    int lane = tid & 31;
    int wid  = tid >> 5;
    int wr   = wid & 3;
    int wc   = wid >> 2;
    int bm   = blockIdx.x * 128;

    int arow = tid >> 3;
    int acol = (tid & 7) * 4;
    bool av[4];
    long gA[4];
#pragma unroll
    for (int i = 0; i < 4; i++) {
        int r = bm + arow + 32 * i;
        av[i] = r < NNODES;
        gA[i] = (long)r * FIN;
    }
    unsigned aStOff = SWZ32(arow, acol >> 3) + ((acol & 4) << 1);

    int lrow = tid >> 2, lchk = tid & 3;
    unsigned sBo0 = SWZ32(lrow, lchk), sBo1 = SWZ32(lrow + 64, lchk);

    int sub = lane >> 3, r8 = lane & 7;
    unsigned aOff[2][2], bOff[4][2];
#pragma unroll
    for (int mt = 0; mt < 2; mt++) {
        int row = wr * 32 + mt * 16 + (sub & 1) * 8 + r8;
#pragma unroll
        for (int ks = 0; ks < 2; ks++)
            aOff[mt][ks] = SWZ32(row, (sub >> 1) + 2 * ks);
    }
#pragma unroll
    for (int np = 0; np < 4; np++) {
        int row = wc * 64 + np * 16 + (sub >> 1) * 8 + r8;
#pragma unroll
        for (int ks = 0; ks < 2; ks++)
            bOff[np][ks] = SWZ32(row, (sub & 1) + 2 * ks);
    }

    float acc[2][8][4];
#pragma unroll
    for (int mt = 0; mt < 2; mt++)
#pragma unroll
        for (int nt = 0; nt < 8; nt++)
#pragma unroll
            for (int j = 0; j < 4; j++) acc[mt][nt][j] = 0.f;

    const int NIT = FIN / 32;   // 16

    auto issueB = [&](int it, int b) {
        int koff = it * 32;
        cpasync16(base + BH  + b * TILEB + sBo0, &g_Bth[(long)lrow * FIN + koff + lchk * 8]);
        cpasync16(base + BH  + b * TILEB + sBo1, &g_Bth[(long)(lrow + 64) * FIN + koff + lchk * 8]);
        cpasync16(base + BMo + b * TILEB + sBo0, &g_Btm[(long)lrow * FIN + koff + lchk * 8]);
        cpasync16(base + BMo + b * TILEB + sBo1, &g_Btm[(long)(lrow + 64) * FIN + koff + lchk * 8]);
    };
    auto loadA = [&](int it, float4* ra) {
        int koff = it * 32 + acol;
#pragma unroll
        for (int i = 0; i < 4; i++)
            ra[i] = av[i] ? *(const float4*)&X[gA[i] + koff]
                          : make_float4(0.f, 0.f, 0.f, 0.f);
    };

    float4 ra[4];
    issueB(0, 0);
    asm volatile("cp.async.commit_group;" ::);
    loadA(0, ra);

    for (int it = 0; it < NIT; it++) {
        int buf = it & 1;
        // A: fp32 -> single fp16, store to smem
#pragma unroll
        for (int i = 0; i < 4; i++) {
            float f[4] = {ra[i].x, ra[i].y, ra[i].z, ra[i].w};
            __half h[4];
#pragma unroll
            for (int j = 0; j < 4; j++) h[j] = __float2half_rn(f[j]);
            unsigned off = aStOff + 32 * i * 64;
            *(uint2*)(dynsmem + AH + buf * TILEB + off) = *(uint2*)h;
        }
        if (it + 1 < NIT) {
            loadA(it + 1, ra);
            issueB(it + 1, buf ^ 1);
            asm volatile("cp.async.commit_group;" ::);
            asm volatile("cp.async.wait_group 1;" ::);
        } else {
            asm volatile("cp.async.wait_group 0;" ::);
        }
        __syncthreads();

        unsigned ah  = base + AH  + buf * TILEB;
        unsigned bh  = base + BH  + buf * TILEB;
        unsigned bmm = base + BMo + buf * TILEB;
#pragma unroll
        for (int ks = 0; ks < 2; ks++) {
            unsigned bhf[4][4], bmf[4][4];
#pragma unroll
            for (int np = 0; np < 4; np++) {
                ldmx4(bhf[np], bh  + bOff[np][ks]);
                ldmx4(bmf[np], bmm + bOff[np][ks]);
            }
#pragma unroll
            for (int mt = 0; mt < 2; mt++) {
                unsigned ahf[4];
                ldmx4(ahf, ah + aOff[mt][ks]);
#pragma unroll
                for (int nt = 0; nt < 8; nt++) {
                    const unsigned* ph = &bhf[nt >> 1][(nt & 1) * 2];
                    const unsigned* pm = &bmf[nt >> 1][(nt & 1) * 2];
                    mma16816h(acc[mt][nt], ahf, ph);
                    mma16816h(acc[mt][nt], ahf, pm);
                }
            }
        }
        __syncthreads();
    }

    int g = lane >> 2, t = lane & 3;
#pragma unroll
    for (int mt = 0; mt < 2; mt++) {
        int r0 = bm + wr * 32 + mt * 16 + g;
        int r1 = r0 + 8;
#pragma unroll
        for (int nt = 0; nt < 8; nt++) {
            int col = wc * 64 + nt * 8 + t * 2;
            if (r0 < NNODES)
                *(float2*)&g_h1[(long)r0 * F1 + col] = make_float2(acc[mt][nt][0], acc[mt][nt][1]);
            if (r1 < NNODES)
                *(float2*)&g_h1[(long)r1 * F1 + col] = make_float2(acc[mt][nt][2], acc[mt][nt][3]);
        }
    }
    // fused coeff1
#pragma unroll
    for (int mt = 0; mt < 2; mt++) {
        int r0 = bm + wr * 32 + mt * 16 + g;
        int r1 = r0 + 8;
#pragma unroll
        for (int hh = 0; hh < 4; hh++) {
            float s0 = 0.f, d0 = 0.f, s1 = 0.f, d1 = 0.f;
#pragma unroll
            for (int q = 0; q < 2; q++) {
                int nt  = 2 * hh + q;
                int col = wc * 64 + nt * 8 + t * 2;
                float asv0 = __ldg(&att_s[col]), asv1 = __ldg(&att_s[col + 1]);
                float adv0 = __ldg(&att_d[col]), adv1 = __ldg(&att_d[col + 1]);
                s0 += acc[mt][nt][0] * asv0 + acc[mt][nt][1] * asv1;
                d0 += acc[mt][nt][0] * adv0 + acc[mt][nt][1] * adv1;
                s1 += acc[mt][nt][2] * asv0 + acc[mt][nt][3] * asv1;
                d1 += acc[mt][nt][2] * adv0 + acc[mt][nt][3] * adv1;
            }
#pragma unroll
            for (int o = 1; o <= 2; o <<= 1) {
                s0 += __shfl_xor_sync(0xFFFFFFFFu, s0, o);
                d0 += __shfl_xor_sync(0xFFFFFFFFu, d0, o);
                s1 += __shfl_xor_sync(0xFFFFFFFFu, s1, o);
                d1 += __shfl_xor_sync(0xFFFFFFFFu, d1, o);
            }
            if (t == 0) {
                int gh = wc * 4 + hh;
                if (r0 < NNODES) { g_as1[r0 * H1N + gh] = s0; g_ad1[r0 * H1N + gh] = d0; }
                if (r1 < NNODES) { g_as1[r1 * H1N + gh] = s1; g_ad1[r1 * H1N + gh] = d1; }
            }
        }
    }
}

// ---------------- layer-1 aggregation: direct-exp softmax, node range ------
__global__ void k_agg1(const float* __restrict__ b1, int n0, int n1) {
    int gtid = blockIdx.x * blockDim.x + threadIdx.x;
    int n    = n0 + (gtid >> 5);
    int lane = threadIdx.x & 31;
    if (n >= n1) return;
    int h = lane >> 2;
    int beg = g_rowptr[n], end = g_rowptr[n + 1];
    float adst = g_ad1[n * H1N + h];
    float s = 0.f;
    float ax = 0.f, ay = 0.f, az = 0.f, aw = 0.f;

    int   s_p2 = (beg + 1 < end) ? __ldg(&g_csr[beg + 1]) : 0;
    float e_p1 = 0.f;
    float4 v_p1 = make_float4(0.f, 0.f, 0.f, 0.f);
    if (beg < end) {
        int s0 = __ldg(&g_csr[beg]);
        e_p1 = g_as1[s0 * H1N + h];
        v_p1 = *(const float4*)&g_h1[(long)s0 * F1 + lane * 4];
    }
    for (int j = beg; j < end; j++) {
        float  e_c = e_p1 + adst;
        float4 v   = v_p1;
        int s_nxt = s_p2;
        if (j + 2 < end) s_p2 = __ldg(&g_csr[j + 2]);
        if (j + 1 < end) {
            e_p1 = g_as1[s_nxt * H1N + h];
            v_p1 = *(const float4*)&g_h1[(long)s_nxt * F1 + lane * 4];
        }
        float e = (e_c > 0.f) ? e_c : 0.2f * e_c;
        float w = __expf(fminf(e, 80.f));
        s  += w;
        ax += w * v.x;
        ay += w * v.y;
        az += w * v.z;
        aw += w * v.w;
    }
    float inv = 1.f / s;
    float o[4];
    o[0] = ax * inv + b1[lane * 4 + 0];
    o[1] = ay * inv + b1[lane * 4 + 1];
    o[2] = az * inv + b1[lane * 4 + 2];
    o[3] = aw * inv + b1[lane * 4 + 3];
#pragma unroll
    for (int i = 0; i < 4; i++)
        o[i] = (o[i] > 0.f) ? o[i] : (__expf(o[i]) - 1.f);
    *(float4*)&g_h1a[(long)n * F1 + lane * 4] = *(float4*)o;
}

// ---------------- GEMM2 + fused coeff2 (4x5 thread tile, 64-row blocks) ----
#define GS2_BYTES ((64 * 132 + 40 * 132 + 64 * 41) * 4)
__global__ __launch_bounds__(128) void k_gemm2(const float* __restrict__ W2,
                                               const float* __restrict__ att_s,
                                               const float* __restrict__ att_d,
                                               int n0, int n1) {
    float* hs  = (float*)dynsmem;        // [64][132]
    float* wst = hs + 64 * 132;          // [40][132]  W2 transposed
    float* h2s = wst + 40 * 132;         // [64][41]
    int r0  = n0 + blockIdx.x * 64;
    int tid = threadIdx.x;

    for (int i = tid; i < F2 * F1; i += 128) {
        int k = i / F2, c = i - k * F2;
        wst[c * 132 + k] = W2[i];
    }
    for (int i = tid; i < 64 * 32; i += 128) {
        int r = i >> 5, k4 = i & 31;
        int gr = r0 + r;
        float4 v = (gr < n1) ? *(const float4*)&g_h1a[(long)gr * F1 + k4 * 4]
                             : make_float4(0.f, 0.f, 0.f, 0.f);
        *(float4*)&hs[r * 132 + k4 * 4] = v;
    }
    __syncthreads();

    int rowg = tid >> 3;
    int colg = tid & 7;
    float acc[4][5];
#pragma unroll
    for (int i = 0; i < 4; i++)
#pragma unroll
        for (int j = 0; j < 5; j++) acc[i][j] = 0.f;

    for (int k4 = 0; k4 < 32; k4++) {
        float4 w[5];
#pragma unroll
        for (int j = 0; j < 5; j++)
            w[j] = *(float4*)&wst[(colg * 5 + j) * 132 + k4 * 4];
#pragma unroll
        for (int i = 0; i < 4; i++) {
            float4 hv = *(float4*)&hs[(rowg + 16 * i) * 132 + k4 * 4];
#pragma unroll
            for (int j = 0; j < 5; j++)
                acc[i][j] += hv.x * w[j].x + hv.y * w[j].y + hv.z * w[j].z + hv.w * w[j].w;
        }
    }
#pragma unroll
    for (int i = 0; i < 4; i++) {
        int r = rowg + 16 * i;
#pragma unroll
        for (int j = 0; j < 5; j++)
            h2s[r * 41 + colg * 5 + j] = acc[i][j];
    }
    __syncthreads();
    for (int i = tid; i < 64 * F2; i += 128) {
        int r = i / F2, c = i - r * F2;
        int gr = r0 + r;
        if (gr < n1) g_h2[(long)gr * F2 + c] = h2s[r * 41 + c];
    }
    if (tid < 64) {
        int gr = r0 + tid;
        if (gr < n1) {
            float s = 0.f, d = 0.f;
#pragma unroll
            for (int cc = 0; cc < F2; cc++) {
                float v = h2s[tid * 41 + cc];
                s += v * __ldg(&att_s[cc]);
                d += v * __ldg(&att_d[cc]);
            }
            g_as2[gr] = s;
            g_ad2[gr] = d;
        }
    }
}

// ---------------- layer-2 aggregation + bias + log_softmax (direct exp) ----
__global__ void k_agg2(const float* __restrict__ b2, float* __restrict__ out) {
    int gtid = blockIdx.x * blockDim.x + threadIdx.x;
    int n    = gtid >> 5;
    int lane = threadIdx.x & 31;
    if (n >= NNODES) return;
    bool has2 = lane < 8;
    int beg = g_rowptr[n], end = g_rowptr[n + 1];
    float adst = g_ad2[n];
    float s = 0.f, a0 = 0.f, a1 = 0.f;

    int   s_p2 = (beg + 1 < end) ? __ldg(&g_csr[beg + 1]) : 0;
    float e_p1 = 0.f, v0_p = 0.f, v1_p = 0.f;
    if (beg < end) {
        int s0 = __ldg(&g_csr[beg]);
        e_p1 = g_as2[s0];
        v0_p = g_h2[(long)s0 * F2 + lane];
        v1_p = has2 ? g_h2[(long)s0 * F2 + 32 + lane] : 0.f;
    }
    for (int j = beg; j < end; j++) {
        float e_c = e_p1 + adst;
        float v0 = v0_p, v1 = v1_p;
        int s_nxt = s_p2;
        if (j + 2 < end) s_p2 = __ldg(&g_csr[j + 2]);
        if (j + 1 < end) {
            e_p1 = g_as2[s_nxt];
            v0_p = g_h2[(long)s_nxt * F2 + lane];
            v1_p = has2 ? g_h2[(long)s_nxt * F2 + 32 + lane] : 0.f;
        }
        float e = (e_c > 0.f) ? e_c : 0.2f * e_c;
        float w = __expf(fminf(e, 80.f));
        s  += w;
        a0 += w * v0;
        a1 += w * v1;
    }
    float inv = 1.f / s;
    float x0 = a0 * inv + b2[lane];
    float x1 = has2 ? (a1 * inv + b2[32 + lane]) : -1e30f;
    float mx = fmaxf(x0, x1);
#pragma unroll
    for (int o = 16; o; o >>= 1) mx = fmaxf(mx, __shfl_xor_sync(0xFFFFFFFFu, mx, o));
    float se = __expf(x0 - mx) + (has2 ? __expf(x1 - mx) : 0.f);
#pragma unroll
    for (int o = 16; o; o >>= 1) se += __shfl_xor_sync(0xFFFFFFFFu, se, o);
    float lse = mx + logf(se);
    out[(long)n * F2 + lane] = x0 - lse;
    if (has2) out[(long)n * F2 + 32 + lane] = x1 - lse;
}

// ---------------- launch ----------------
extern "C" void kernel_launch(void* const* d_in, const int* in_sizes, int n_in,
                              void* d_out, int out_size) {
    const float* x   = (const float*)d_in[0];
    const int*   ei  = (const int*)d_in[1];
    const float* W1  = (const float*)d_in[2];
    const float* as1 = (const float*)d_in[3];
    const float* ad1 = (const float*)d_in[4];
    const float* b1  = (const float*)d_in[5];
    const float* W2  = (const float*)d_in[6];
    const float* as2 = (const float*)d_in[7];
    const float* ad2 = (const float*)d_in[8];
    const float* b2  = (const float*)d_in[9];
    float*       out = (float*)d_out;

    int E    = in_sizes[1] / 2;
    if (E > EMAX) E = EMAX;
    int Etot = E + NNODES;
    int nb   = (NNODES + 1023) / 1024;

    static cudaStream_t sA = nullptr, sB = nullptr;
    static cudaEvent_t  e0, eA1, eB, eA2;
    if (!sA) {
        cudaStreamCreateWithFlags(&sA, cudaStreamNonBlocking);
        cudaStreamCreateWithFlags(&sB, cudaStreamNonBlocking);
        cudaEventCreateWithFlags(&e0,  cudaEventDisableTiming);
        cudaEventCreateWithFlags(&eA1, cudaEventDisableTiming);
        cudaEventCreateWithFlags(&eB,  cudaEventDisableTiming);
        cudaEventCreateWithFlags(&eA2, cudaEventDisableTiming);
        cudaFuncSetAttribute(k_gemm1_mma, cudaFuncAttributeMaxDynamicSharedMemorySize, 6 * TILEB);
        cudaFuncSetAttribute(k_gemm2, cudaFuncAttributeMaxDynamicSharedMemorySize, GS2_BYTES);
    }

    cudaEventRecord(e0, 0);
    cudaStreamWaitEvent(sA, e0, 0);
    cudaStreamWaitEvent(sB, e0, 0);

    const int NLO = NH0;
    const int NHI = NNODES - NH0;

    // enqueue order: launch index 3 = k_gemm1_mma (ncu window)
    k_zero_counts<<<(NNODES + 255) / 256, 256, 0, sB>>>();                    // 0
    k_count<<<(Etot + 255) / 256, 256, 0, sB>>>(ei, E, Etot);                 // 1
    k_splitB<<<(FIN * F1 + 255) / 256, 256, 0, sA>>>(W1);                     // 2
    k_gemm1_mma<<<(NNODES + 127) / 128, 256, 6 * TILEB, sA>>>(x, as1, ad1);   // 3 <- profiled
    cudaEventRecord(eA1, sA);
    k_scan1<<<nb, 1024, 0, sB>>>();                                           // 4
    k_scan2<<<1, 64, 0, sB>>>(nb);                                            // 5
    k_scan3<<<(NNODES + 255) / 256, 256, 0, sB>>>(Etot);                      // 6
    k_fill<<<(Etot + 255) / 256, 256, 0, sB>>>(ei, E, Etot);                  // 7
    cudaEventRecord(eB, sB);

    // stream A: hi-half aggregation + gemm2
    cudaStreamWaitEvent(sA, eB, 0);
    k_agg1<<<(NHI * 32 + 255) / 256, 256, 0, sA>>>(b1, NH0, NNODES);          // 8
    k_gemm2<<<(NHI + 63) / 64, 128, GS2_BYTES, sA>>>(W2, as2, ad2, NH0, NNODES); // 9
    cudaEventRecord(eA2, sA);

    // default stream: lo-half aggregation + gemm2, then final agg2
    cudaStreamWaitEvent(0, eA1, 0);
    cudaStreamWaitEvent(0, eB, 0);
    k_agg1<<<(NLO * 32 + 255) / 256, 256>>>(b1, 0, NH0);                      // 10
    k_gemm2<<<(NLO + 63) / 64, 128, GS2_BYTES>>>(W2, as2, ad2, 0, NH0);       // 11
    cudaStreamWaitEvent(0, eA2, 0);
    k_agg2<<<(NNODES * 32 + 255) / 256, 256>>>(b2, out);                      // 12
}

// round 12
// speedup vs baseline: 1.3353x; 1.1118x over previous
#include <cuda_runtime.h>
#include <cuda_fp16.h>

#define NNODES 50000
#define FIN    512
#define H1N    8
#define C1N    16
#define F1     128      // H1*C1
#define F2     40
#define EMAX   800000
#define ETOTMAX (EMAX + NNODES)
#define NH0    25024    // lo/hi node split (64-aligned)

// ---------------- static scratch ----------------
__device__ float g_h1 [NNODES * F1];
__device__ float g_h1a[NNODES * F1];
__device__ float g_as1[NNODES * H1N];
__device__ float g_ad1[NNODES * H1N];
__device__ float g_h2 [NNODES * F2];
__device__ float g_as2[NNODES];
__device__ float g_ad2[NNODES];
__device__ int   g_counts[NNODES];
__device__ int   g_rowptr[NNODES + 1];
__device__ int   g_cursor[NNODES];
__device__ int   g_csr[ETOTMAX];
__device__ int   g_bsum[64];

__device__ __half g_Bt[F1 * FIN];   // fp16 W1, transposed [n][k]

// ---------------- CSR build ----------------
__global__ void k_zero_counts() {
    int i = blockIdx.x * blockDim.x + threadIdx.x;
    if (i < NNODES) g_counts[i] = 0;
}

__global__ void k_count(const int* __restrict__ ei, int E, int Etot) {
    int i = blockIdx.x * blockDim.x + threadIdx.x;
    if (i >= Etot) return;
    int d = (i < E) ? ei[E + i] : (i - E);
    if (d < 0 || d >= NNODES) return;
    atomicAdd(&g_counts[d], 1);
}

__global__ void k_scan1() {
    __shared__ int tmp[1024];
    int t = threadIdx.x;
    int gid = blockIdx.x * 1024 + t;
    int v = (gid < NNODES) ? g_counts[gid] : 0;
    tmp[t] = v;
    __syncthreads();
    for (int off = 1; off < 1024; off <<= 1) {
        int x = (t >= off) ? tmp[t - off] : 0;
        __syncthreads();
        tmp[t] += x;
        __syncthreads();
    }
    if (gid < NNODES) g_rowptr[gid] = tmp[t] - v;
    if (t == 1023) g_bsum[blockIdx.x] = tmp[1023];
}

__global__ void k_scan2(int nb) {
    __shared__ int sh[64];
    int t = threadIdx.x;
    int v = (t < nb) ? g_bsum[t] : 0;
    sh[t] = v;
    __syncthreads();
    for (int off = 1; off < 64; off <<= 1) {
        int x = (t >= off) ? sh[t - off] : 0;
        __syncthreads();
        sh[t] += x;
        __syncthreads();
    }
    if (t < nb) g_bsum[t] = sh[t] - v;   // exclusive
}

__global__ void k_scan3(int Etot) {
    int gid = blockIdx.x * blockDim.x + threadIdx.x;
    if (gid < NNODES) {
        int v = g_rowptr[gid] + g_bsum[gid >> 10];
        g_rowptr[gid] = v;
        g_cursor[gid] = v;
    }
    if (gid == 0) g_rowptr[NNODES] = Etot;
}

__global__ void k_fill(const int* __restrict__ ei, int E, int Etot) {
    int i = blockIdx.x * blockDim.x + threadIdx.x;
    if (i >= Etot) return;
    int s, d;
    if (i < E) { s = ei[i]; d = ei[E + i]; }
    else       { s = d = i - E; }
    if (d < 0 || d >= NNODES || s < 0 || s >= NNODES) return;
    int pos = atomicAdd(&g_cursor[d], 1);
    if (pos < ETOTMAX) g_csr[pos] = s;
}

// ---------------- fp16 convert + transpose of W1 (tiny: 128KB) -------------
__global__ void k_convB(const float* __restrict__ W1) {
    int i = blockIdx.x * blockDim.x + threadIdx.x;
    if (i >= FIN * F1) return;
    int k = i / F1, n = i % F1;
    g_Bt[n * FIN + k] = __float2half_rn(W1[i]);
}

// ---------------- GEMM1 + fused coeff1 epilogue ----------------
// h1 = x@W1, pure fp16 operands, fp32 accum. 1 MMA per fragment pair.
#define SWZ32(row, chk) ((row) * 64 + (((chk) ^ (((row) >> 1) & 3)) << 4))
#define TILEB 8192   // one 128x32 fp16 tile

__device__ __forceinline__ void ldmx4(unsigned* r, unsigned addr) {
    asm volatile("ldmatrix.sync.aligned.m8n8.x4.shared.b16 {%0,%1,%2,%3}, [%4];"
                 : "=r"(r[0]), "=r"(r[1]), "=r"(r[2]), "=r"(r[3]) : "r"(addr));
}

__device__ __forceinline__ void mma16816h(float* c, const unsigned* a, const unsigned* b) {
    asm volatile(
        "mma.sync.aligned.m16n8k16.row.col.f32.f16.f16.f32 "
        "{%0,%1,%2,%3}, {%4,%5,%6,%7}, {%8,%9}, {%0,%1,%2,%3};"
        : "+f"(c[0]), "+f"(c[1]), "+f"(c[2]), "+f"(c[3])
        : "r"(a[0]), "r"(a[1]), "r"(a[2]), "r"(a[3]), "r"(b[0]), "r"(b[1]));
}

__device__ __forceinline__ void cpasync16(unsigned saddr, const void* gaddr) {
    asm volatile("cp.async.cg.shared.global [%0], [%1], 16;"
                 :: "r"(saddr), "l"(gaddr));
}

extern __shared__ __align__(16) unsigned char dynsmem[];

__global__ __launch_bounds__(256) void k_gemm1_mma(const float* __restrict__ X,
                                                   const float* __restrict__ att_s,
                                                   const float* __restrict__ att_d) {
    // smem regions (double buffered): AH [0,2T), BH [2T,4T)
    const int AH = 0, BH = 2 * TILEB;
    unsigned base = (unsigned)__cvta_generic_to_shared(dynsmem);

    int tid  = threadIdx.x;
    int lane = tid & 31;
    int wid  = tid >> 5;
    int wr   = wid & 3;
    int wc   = wid >> 2;
    int bm   = blockIdx.x * 128;

    int arow = tid >> 3;
    int acol = (tid & 7) * 4;
    bool av[4];
    long gA[4];
#pragma unroll
    for (int i = 0; i < 4; i++) {
        int r = bm + arow + 32 * i;
        av[i] = r < NNODES;
        gA[i] = (long)r * FIN;
    }
    unsigned aStOff = SWZ32(arow, acol >> 3) + ((acol & 4) << 1);

    int lrow = tid >> 2, lchk = tid & 3;
    unsigned sBo0 = SWZ32(lrow, lchk), sBo1 = SWZ32(lrow + 64, lchk);

    int sub = lane >> 3, r8 = lane & 7;
    unsigned aOff[2][2], bOff[4][2];
#pragma unroll
    for (int mt = 0; mt < 2; mt++) {
        int row = wr * 32 + mt * 16 + (sub & 1) * 8 + r8;
#pragma unroll
        for (int ks = 0; ks < 2; ks++)
            aOff[mt][ks] = SWZ32(row, (sub >> 1) + 2 * ks);
    }
#pragma unroll
    for (int np = 0; np < 4; np++) {
        int row = wc * 64 + np * 16 + (sub >> 1) * 8 + r8;
#pragma unroll
        for (int ks = 0; ks < 2; ks++)
            bOff[np][ks] = SWZ32(row, (sub & 1) + 2 * ks);
    }

    float acc[2][8][4];
#pragma unroll
    for (int mt = 0; mt < 2; mt++)
#pragma unroll
        for (int nt = 0; nt < 8; nt++)
#pragma unroll
            for (int j = 0; j < 4; j++) acc[mt][nt][j] = 0.f;

    const int NIT = FIN / 32;   // 16

    auto issueB = [&](int it, int b) {
        int koff = it * 32;
        cpasync16(base + BH + b * TILEB + sBo0, &g_Bt[(long)lrow * FIN + koff + lchk * 8]);
        cpasync16(base + BH + b * TILEB + sBo1, &g_Bt[(long)(lrow + 64) * FIN + koff + lchk * 8]);
    };
    auto loadA = [&](int it, float4* ra) {
        int koff = it * 32 + acol;
#pragma unroll
        for (int i = 0; i < 4; i++)
            ra[i] = av[i] ? *(const float4*)&X[gA[i] + koff]
                          : make_float4(0.f, 0.f, 0.f, 0.f);
    };

    float4 ra[4];
    issueB(0, 0);
    asm volatile("cp.async.commit_group;" ::);
    loadA(0, ra);

    for (int it = 0; it < NIT; it++) {
        int buf = it & 1;
#pragma unroll
        for (int i = 0; i < 4; i++) {
            float f[4] = {ra[i].x, ra[i].y, ra[i].z, ra[i].w};
            __half h[4];
#pragma unroll
            for (int j = 0; j < 4; j++) h[j] = __float2half_rn(f[j]);
            unsigned off = aStOff + 32 * i * 64;
            *(uint2*)(dynsmem + AH + buf * TILEB + off) = *(uint2*)h;
        }
        if (it + 1 < NIT) {
            loadA(it + 1, ra);
            issueB(it + 1, buf ^ 1);
            asm volatile("cp.async.commit_group;" ::);
            asm volatile("cp.async.wait_group 1;" ::);
        } else {
            asm volatile("cp.async.wait_group 0;" ::);
        }
        __syncthreads();

        unsigned ah = base + AH + buf * TILEB;
        unsigned bh = base + BH + buf * TILEB;
#pragma unroll
        for (int ks = 0; ks < 2; ks++) {
            unsigned bhf[4][4];
#pragma unroll
            for (int np = 0; np < 4; np++) ldmx4(bhf[np], bh + bOff[np][ks]);
#pragma unroll
            for (int mt = 0; mt < 2; mt++) {
                unsigned ahf[4];
                ldmx4(ahf, ah + aOff[mt][ks]);
#pragma unroll
                for (int nt = 0; nt < 8; nt++)
                    mma16816h(acc[mt][nt], ahf, &bhf[nt >> 1][(nt & 1) * 2]);
            }
        }
        __syncthreads();
    }

    int g = lane >> 2, t = lane & 3;
#pragma unroll
    for (int mt = 0; mt < 2; mt++) {
        int r0 = bm + wr * 32 + mt * 16 + g;
        int r1 = r0 + 8;
#pragma unroll
        for (int nt = 0; nt < 8; nt++) {
            int col = wc * 64 + nt * 8 + t * 2;
            if (r0 < NNODES)
                *(float2*)&g_h1[(long)r0 * F1 + col] = make_float2(acc[mt][nt][0], acc[mt][nt][1]);
            if (r1 < NNODES)
                *(float2*)&g_h1[(long)r1 * F1 + col] = make_float2(acc[mt][nt][2], acc[mt][nt][3]);
        }
    }
    // fused coeff1
#pragma unroll
    for (int mt = 0; mt < 2; mt++) {
        int r0 = bm + wr * 32 + mt * 16 + g;
        int r1 = r0 + 8;
#pragma unroll
        for (int hh = 0; hh < 4; hh++) {
            float s0 = 0.f, d0 = 0.f, s1 = 0.f, d1 = 0.f;
#pragma unroll
            for (int q = 0; q < 2; q++) {
                int nt  = 2 * hh + q;
                int col = wc * 64 + nt * 8 + t * 2;
                float asv0 = __ldg(&att_s[col]), asv1 = __ldg(&att_s[col + 1]);
                float adv0 = __ldg(&att_d[col]), adv1 = __ldg(&att_d[col + 1]);
                s0 += acc[mt][nt][0] * asv0 + acc[mt][nt][1] * asv1;
                d0 += acc[mt][nt][0] * adv0 + acc[mt][nt][1] * adv1;
                s1 += acc[mt][nt][2] * asv0 + acc[mt][nt][3] * asv1;
                d1 += acc[mt][nt][2] * adv0 + acc[mt][nt][3] * adv1;
            }
#pragma unroll
            for (int o = 1; o <= 2; o <<= 1) {
                s0 += __shfl_xor_sync(0xFFFFFFFFu, s0, o);
                d0 += __shfl_xor_sync(0xFFFFFFFFu, d0, o);
                s1 += __shfl_xor_sync(0xFFFFFFFFu, s1, o);
                d1 += __shfl_xor_sync(0xFFFFFFFFu, d1, o);
            }
            if (t == 0) {
                int gh = wc * 4 + hh;
                if (r0 < NNODES) { g_as1[r0 * H1N + gh] = s0; g_ad1[r0 * H1N + gh] = d0; }
                if (r1 < NNODES) { g_as1[r1 * H1N + gh] = s1; g_ad1[r1 * H1N + gh] = d1; }
            }
        }
    }
}

// ---------------- layer-1 aggregation: direct-exp softmax, node range ------
__global__ void k_agg1(const float* __restrict__ b1, int n0, int n1) {
    int gtid = blockIdx.x * blockDim.x + threadIdx.x;
    int n    = n0 + (gtid >> 5);
    int lane = threadIdx.x & 31;
    if (n >= n1) return;
    int h = lane >> 2;
    int beg = g_rowptr[n], end = g_rowptr[n + 1];
    float adst = g_ad1[n * H1N + h];
    float s = 0.f;
    float ax = 0.f, ay = 0.f, az = 0.f, aw = 0.f;

    int   s_p2 = (beg + 1 < end) ? __ldg(&g_csr[beg + 1]) : 0;
    float e_p1 = 0.f;
    float4 v_p1 = make_float4(0.f, 0.f, 0.f, 0.f);
    if (beg < end) {
        int s0 = __ldg(&g_csr[beg]);
        e_p1 = g_as1[s0 * H1N + h];
        v_p1 = *(const float4*)&g_h1[(long)s0 * F1 + lane * 4];
    }
    for (int j = beg; j < end; j++) {
        float  e_c = e_p1 + adst;
        float4 v   = v_p1;
        int s_nxt = s_p2;
        if (j + 2 < end) s_p2 = __ldg(&g_csr[j + 2]);
        if (j + 1 < end) {
            e_p1 = g_as1[s_nxt * H1N + h];
            v_p1 = *(const float4*)&g_h1[(long)s_nxt * F1 + lane * 4];
        }
        float e = (e_c > 0.f) ? e_c : 0.2f * e_c;
        float w = __expf(fminf(e, 80.f));
        s  += w;
        ax += w * v.x;
        ay += w * v.y;
        az += w * v.z;
        aw += w * v.w;
    }
    float inv = 1.f / s;
    float o[4];
    o[0] = ax * inv + b1[lane * 4 + 0];
    o[1] = ay * inv + b1[lane * 4 + 1];
    o[2] = az * inv + b1[lane * 4 + 2];
    o[3] = aw * inv + b1[lane * 4 + 3];
#pragma unroll
    for (int i = 0; i < 4; i++)
        o[i] = (o[i] > 0.f) ? o[i] : (__expf(o[i]) - 1.f);
    *(float4*)&g_h1a[(long)n * F1 + lane * 4] = *(float4*)o;
}

// ---------------- GEMM2 + fused coeff2 (4x5 thread tile, 64-row blocks) ----
#define GS2_BYTES ((64 * 132 + 40 * 132 + 64 * 41) * 4)
__global__ __launch_bounds__(128) void k_gemm2(const float* __restrict__ W2,
                                               const float* __restrict__ att_s,
                                               const float* __restrict__ att_d,
                                               int n0, int n1) {
    float* hs  = (float*)dynsmem;        // [64][132]
    float* wst = hs + 64 * 132;          // [40][132]  W2 transposed
    float* h2s = wst + 40 * 132;         // [64][41]
    int r0  = n0 + blockIdx.x * 64;
    int tid = threadIdx.x;

    for (int i = tid; i < F2 * F1; i += 128) {
        int k = i / F2, c = i - k * F2;
        wst[c * 132 + k] = W2[i];
    }
    for (int i = tid; i < 64 * 32; i += 128) {
        int r = i >> 5, k4 = i & 31;
        int gr = r0 + r;
        float4 v = (gr < n1) ? *(const float4*)&g_h1a[(long)gr * F1 + k4 * 4]
                             : make_float4(0.f, 0.f, 0.f, 0.f);
        *(float4*)&hs[r * 132 + k4 * 4] = v;
    }
    __syncthreads();

    int rowg = tid >> 3;
    int colg = tid & 7;
    float acc[4][5];
#pragma unroll
    for (int i = 0; i < 4; i++)
#pragma unroll
        for (int j = 0; j < 5; j++) acc[i][j] = 0.f;

    for (int k4 = 0; k4 < 32; k4++) {
        float4 w[5];
#pragma unroll
        for (int j = 0; j < 5; j++)
            w[j] = *(float4*)&wst[(colg * 5 + j) * 132 + k4 * 4];
#pragma unroll
        for (int i = 0; i < 4; i++) {
            float4 hv = *(float4*)&hs[(rowg + 16 * i) * 132 + k4 * 4];
#pragma unroll
            for (int j = 0; j < 5; j++)
                acc[i][j] += hv.x * w[j].x + hv.y * w[j].y + hv.z * w[j].z + hv.w * w[j].w;
        }
    }
#pragma unroll
    for (int i = 0; i < 4; i++) {
        int r = rowg + 16 * i;
#pragma unroll
        for (int j = 0; j < 5; j++)
            h2s[r * 41 + colg * 5 + j] = acc[i][j];
    }
    __syncthreads();
    for (int i = tid; i < 64 * F2; i += 128) {
        int r = i / F2, c = i - r * F2;
        int gr = r0 + r;
        if (gr < n1) g_h2[(long)gr * F2 + c] = h2s[r * 41 + c];
    }
    if (tid < 64) {
        int gr = r0 + tid;
        if (gr < n1) {
            float s = 0.f, d = 0.f;
#pragma unroll
            for (int cc = 0; cc < F2; cc++) {
                float v = h2s[tid * 41 + cc];
                s += v * __ldg(&att_s[cc]);
                d += v * __ldg(&att_d[cc]);
            }
            g_as2[gr] = s;
            g_ad2[gr] = d;
        }
    }
}

// ---------------- layer-2 aggregation + bias + log_softmax (direct exp) ----
__global__ void k_agg2(const float* __restrict__ b2, float* __restrict__ out) {
    int gtid = blockIdx.x * blockDim.x + threadIdx.x;
    int n    = gtid >> 5;
    int lane = threadIdx.x & 31;
    if (n >= NNODES) return;
    bool has2 = lane < 8;
    int beg = g_rowptr[n], end = g_rowptr[n + 1];
    float adst = g_ad2[n];
    float s = 0.f, a0 = 0.f, a1 = 0.f;

    int   s_p2 = (beg + 1 < end) ? __ldg(&g_csr[beg + 1]) : 0;
    float e_p1 = 0.f, v0_p = 0.f, v1_p = 0.f;
    if (beg < end) {
        int s0 = __ldg(&g_csr[beg]);
        e_p1 = g_as2[s0];
        v0_p = g_h2[(long)s0 * F2 + lane];
        v1_p = has2 ? g_h2[(long)s0 * F2 + 32 + lane] : 0.f;
    }
    for (int j = beg; j < end; j++) {
        float e_c = e_p1 + adst;
        float v0 = v0_p, v1 = v1_p;
        int s_nxt = s_p2;
        if (j + 2 < end) s_p2 = __ldg(&g_csr[j + 2]);
        if (j + 1 < end) {
            e_p1 = g_as2[s_nxt];
            v0_p = g_h2[(long)s_nxt * F2 + lane];
            v1_p = has2 ? g_h2[(long)s_nxt * F2 + 32 + lane] : 0.f;
        }
        float e = (e_c > 0.f) ? e_c : 0.2f * e_c;
        float w = __expf(fminf(e, 80.f));
        s  += w;
        a0 += w * v0;
        a1 += w * v1;
    }
    float inv = 1.f / s;
    float x0 = a0 * inv + b2[lane];
    float x1 = has2 ? (a1 * inv + b2[32 + lane]) : -1e30f;
    float mx = fmaxf(x0, x1);
#pragma unroll
    for (int o = 16; o; o >>= 1) mx = fmaxf(mx, __shfl_xor_sync(0xFFFFFFFFu, mx, o));
    float se = __expf(x0 - mx) + (has2 ? __expf(x1 - mx) : 0.f);
#pragma unroll
    for (int o = 16; o; o >>= 1) se += __shfl_xor_sync(0xFFFFFFFFu, se, o);
    float lse = mx + logf(se);
    out[(long)n * F2 + lane] = x0 - lse;
    if (has2) out[(long)n * F2 + 32 + lane] = x1 - lse;
}

// ---------------- launch ----------------
extern "C" void kernel_launch(void* const* d_in, const int* in_sizes, int n_in,
                              void* d_out, int out_size) {
    const float* x   = (const float*)d_in[0];
    const int*   ei  = (const int*)d_in[1];
    const float* W1  = (const float*)d_in[2];
    const float* as1 = (const float*)d_in[3];
    const float* ad1 = (const float*)d_in[4];
    const float* b1  = (const float*)d_in[5];
    const float* W2  = (const float*)d_in[6];
    const float* as2 = (const float*)d_in[7];
    const float* ad2 = (const float*)d_in[8];
    const float* b2  = (const float*)d_in[9];
    float*       out = (float*)d_out;

    int E    = in_sizes[1] / 2;
    if (E > EMAX) E = EMAX;
    int Etot = E + NNODES;
    int nb   = (NNODES + 1023) / 1024;

    static cudaStream_t sA = nullptr, sB = nullptr;
    static cudaEvent_t  e0, eA1, eB, eA2;
    if (!sA) {
        cudaStreamCreateWithFlags(&sA, cudaStreamNonBlocking);
        cudaStreamCreateWithFlags(&sB, cudaStreamNonBlocking);
        cudaEventCreateWithFlags(&e0,  cudaEventDisableTiming);
        cudaEventCreateWithFlags(&eA1, cudaEventDisableTiming);
        cudaEventCreateWithFlags(&eB,  cudaEventDisableTiming);
        cudaEventCreateWithFlags(&eA2, cudaEventDisableTiming);
        cudaFuncSetAttribute(k_gemm1_mma, cudaFuncAttributeMaxDynamicSharedMemorySize, 4 * TILEB);
        cudaFuncSetAttribute(k_gemm2, cudaFuncAttributeMaxDynamicSharedMemorySize, GS2_BYTES);
    }

    cudaEventRecord(e0, 0);
    cudaStreamWaitEvent(sA, e0, 0);
    cudaStreamWaitEvent(sB, e0, 0);

    const int NLO = NH0;
    const int NHI = NNODES - NH0;

    // enqueue order: launch index 3 = k_gemm1_mma (ncu window)
    k_zero_counts<<<(NNODES + 255) / 256, 256, 0, sB>>>();                    // 0
    k_count<<<(Etot + 255) / 256, 256, 0, sB>>>(ei, E, Etot);                 // 1
    k_convB<<<(FIN * F1 + 255) / 256, 256, 0, sA>>>(W1);                      // 2
    k_gemm1_mma<<<(NNODES + 127) / 128, 256, 4 * TILEB, sA>>>(x, as1, ad1);   // 3 <- profiled
    cudaEventRecord(eA1, sA);
    k_scan1<<<nb, 1024, 0, sB>>>();                                           // 4
    k_scan2<<<1, 64, 0, sB>>>(nb);                                            // 5
    k_scan3<<<(NNODES + 255) / 256, 256, 0, sB>>>(Etot);                      // 6
    k_fill<<<(Etot + 255) / 256, 256, 0, sB>>>(ei, E, Etot);                  // 7
    cudaEventRecord(eB, sB);

    // stream A: hi-half aggregation + gemm2
    cudaStreamWaitEvent(sA, eB, 0);
    k_agg1<<<(NHI * 32 + 255) / 256, 256, 0, sA>>>(b1, NH0, NNODES);          // 8
    k_gemm2<<<(NHI + 63) / 64, 128, GS2_BYTES, sA>>>(W2, as2, ad2, NH0, NNODES); // 9
    cudaEventRecord(eA2, sA);

    // default stream: lo-half aggregation + gemm2, then final agg2
    cudaStreamWaitEvent(0, eA1, 0);
    cudaStreamWaitEvent(0, eB, 0);
    k_agg1<<<(NLO * 32 + 255) / 256, 256>>>(b1, 0, NH0);                      // 10
    k_gemm2<<<(NLO + 63) / 64, 128, GS2_BYTES>>>(W2, as2, ad2, 0, NH0);       // 11
    cudaStreamWaitEvent(0, eA2, 0);
    k_agg2<<<(NNODES * 32 + 255) / 256, 256>>>(b2, out);                      // 12
}

// round 13
// speedup vs baseline: 1.3371x; 1.0014x over previous
#include <cuda_runtime.h>
#include <cuda_fp16.h>

#define NNODES 50000
#define FIN    512
#define H1N    8
#define C1N    16
#define F1     128      // H1*C1
#define F2     40
#define EMAX   800000
#define ETOTMAX (EMAX + NNODES)
#define NH0    25024    // lo/hi node split (64-aligned)

// ---------------- static scratch ----------------
__device__ __half g_h1 [NNODES * F1];   // fp16 layer1 features (gather payload)
__device__ float g_h1a[NNODES * F1];
__device__ float g_as1[NNODES * H1N];
__device__ float g_ad1[NNODES * H1N];
__device__ float g_h2 [NNODES * F2];
__device__ float g_as2[NNODES];
__device__ float g_ad2[NNODES];
__device__ int   g_counts[NNODES];
__device__ int   g_rowptr[NNODES + 1];
__device__ int   g_cursor[NNODES];
__device__ int   g_csr[ETOTMAX];
__device__ int   g_bsum[64];

__device__ __half g_Bt[F1 * FIN];   // fp16 W1, transposed [n][k]

// ---------------- CSR build ----------------
__global__ void k_zero_counts() {
    int i = blockIdx.x * blockDim.x + threadIdx.x;
    if (i < NNODES) g_counts[i] = 0;
}

__global__ void k_count(const int* __restrict__ ei, int E, int Etot) {
    int i = blockIdx.x * blockDim.x + threadIdx.x;
    if (i >= Etot) return;
    int d = (i < E) ? ei[E + i] : (i - E);
    if (d < 0 || d >= NNODES) return;
    atomicAdd(&g_counts[d], 1);
}

__global__ void k_scan1() {
    __shared__ int tmp[1024];
    int t = threadIdx.x;
    int gid = blockIdx.x * 1024 + t;
    int v = (gid < NNODES) ? g_counts[gid] : 0;
    tmp[t] = v;
    __syncthreads();
    for (int off = 1; off < 1024; off <<= 1) {
        int x = (t >= off) ? tmp[t - off] : 0;
        __syncthreads();
        tmp[t] += x;
        __syncthreads();
    }
    if (gid < NNODES) g_rowptr[gid] = tmp[t] - v;
    if (t == 1023) g_bsum[blockIdx.x] = tmp[1023];
}

__global__ void k_scan2(int nb) {
    __shared__ int sh[64];
    int t = threadIdx.x;
    int v = (t < nb) ? g_bsum[t] : 0;
    sh[t] = v;
    __syncthreads();
    for (int off = 1; off < 64; off <<= 1) {
        int x = (t >= off) ? sh[t - off] : 0;
        __syncthreads();
        sh[t] += x;
        __syncthreads();
    }
    if (t < nb) g_bsum[t] = sh[t] - v;   // exclusive
}

__global__ void k_scan3(int Etot) {
    int gid = blockIdx.x * blockDim.x + threadIdx.x;
    if (gid < NNODES) {
        int v = g_rowptr[gid] + g_bsum[gid >> 10];
        g_rowptr[gid] = v;
        g_cursor[gid] = v;
    }
    if (gid == 0) g_rowptr[NNODES] = Etot;
}

__global__ void k_fill(const int* __restrict__ ei, int E, int Etot) {
    int i = blockIdx.x * blockDim.x + threadIdx.x;
    if (i >= Etot) return;
    int s, d;
    if (i < E) { s = ei[i]; d = ei[E + i]; }
    else       { s = d = i - E; }
    if (d < 0 || d >= NNODES || s < 0 || s >= NNODES) return;
    int pos = atomicAdd(&g_cursor[d], 1);
    if (pos < ETOTMAX) g_csr[pos] = s;
}

// ---------------- fp16 convert + transpose of W1 (tiny: 128KB) -------------
__global__ void k_convB(const float* __restrict__ W1) {
    int i = blockIdx.x * blockDim.x + threadIdx.x;
    if (i >= FIN * F1) return;
    int k = i / F1, n = i % F1;
    g_Bt[n * FIN + k] = __float2half_rn(W1[i]);
}

// ---------------- GEMM1 + fused coeff1 epilogue ----------------
// h1 = x@W1, pure fp16 operands, fp32 accum, fp16 h1 store.
#define SWZ32(row, chk) ((row) * 64 + (((chk) ^ (((row) >> 1) & 3)) << 4))
#define TILEB 8192   // one 128x32 fp16 tile

__device__ __forceinline__ void ldmx4(unsigned* r, unsigned addr) {
    asm volatile("ldmatrix.sync.aligned.m8n8.x4.shared.b16 {%0,%1,%2,%3}, [%4];"
                 : "=r"(r[0]), "=r"(r[1]), "=r"(r[2]), "=r"(r[3]) : "r"(addr));
}

__device__ __forceinline__ void mma16816h(float* c, const unsigned* a, const unsigned* b) {
    asm volatile(
        "mma.sync.aligned.m16n8k16.row.col.f32.f16.f16.f32 "
        "{%0,%1,%2,%3}, {%4,%5,%6,%7}, {%8,%9}, {%0,%1,%2,%3};"
        : "+f"(c[0]), "+f"(c[1]), "+f"(c[2]), "+f"(c[3])
        : "r"(a[0]), "r"(a[1]), "r"(a[2]), "r"(a[3]), "r"(b[0]), "r"(b[1]));
}

__device__ __forceinline__ void cpasync16(unsigned saddr, const void* gaddr) {
    asm volatile("cp.async.cg.shared.global [%0], [%1], 16;"
                 :: "r"(saddr), "l"(gaddr));
}

extern __shared__ __align__(16) unsigned char dynsmem[];

__global__ __launch_bounds__(256) void k_gemm1_mma(const float* __restrict__ X,
                                                   const float* __restrict__ att_s,
                                                   const float* __restrict__ att_d) {
    const int AH = 0, BH = 2 * TILEB;
    unsigned base = (unsigned)__cvta_generic_to_shared(dynsmem);

    int tid  = threadIdx.x;
    int lane = tid & 31;
    int wid  = tid >> 5;
    int wr   = wid & 3;
    int wc   = wid >> 2;
    int bm   = blockIdx.x * 128;

    int arow = tid >> 3;
    int acol = (tid & 7) * 4;
    bool av[4];
    long gA[4];
#pragma unroll
    for (int i = 0; i < 4; i++) {
        int r = bm + arow + 32 * i;
        av[i] = r < NNODES;
        gA[i] = (long)r * FIN;
    }
    unsigned aStOff = SWZ32(arow, acol >> 3) + ((acol & 4) << 1);

    int lrow = tid >> 2, lchk = tid & 3;
    unsigned sBo0 = SWZ32(lrow, lchk), sBo1 = SWZ32(lrow + 64, lchk);

    int sub = lane >> 3, r8 = lane & 7;
    unsigned aOff[2][2], bOff[4][2];
#pragma unroll
    for (int mt = 0; mt < 2; mt++) {
        int row = wr * 32 + mt * 16 + (sub & 1) * 8 + r8;
#pragma unroll
        for (int ks = 0; ks < 2; ks++)
            aOff[mt][ks] = SWZ32(row, (sub >> 1) + 2 * ks);
    }
#pragma unroll
    for (int np = 0; np < 4; np++) {
        int row = wc * 64 + np * 16 + (sub >> 1) * 8 + r8;
#pragma unroll
        for (int ks = 0; ks < 2; ks++)
            bOff[np][ks] = SWZ32(row, (sub & 1) + 2 * ks);
    }

    float acc[2][8][4];
#pragma unroll
    for (int mt = 0; mt < 2; mt++)
#pragma unroll
        for (int nt = 0; nt < 8; nt++)
#pragma unroll
            for (int j = 0; j < 4; j++) acc[mt][nt][j] = 0.f;

    const int NIT = FIN / 32;   // 16

    auto issueB = [&](int it, int b) {
        int koff = it * 32;
        cpasync16(base + BH + b * TILEB + sBo0, &g_Bt[(long)lrow * FIN + koff + lchk * 8]);
        cpasync16(base + BH + b * TILEB + sBo1, &g_Bt[(long)(lrow + 64) * FIN + koff + lchk * 8]);
    };
    auto loadA = [&](int it, float4* ra) {
        int koff = it * 32 + acol;
#pragma unroll
        for (int i = 0; i < 4; i++)
            ra[i] = av[i] ? *(const float4*)&X[gA[i] + koff]
                          : make_float4(0.f, 0.f, 0.f, 0.f);
    };

    float4 ra[4];
    issueB(0, 0);
    asm volatile("cp.async.commit_group;" ::);
    loadA(0, ra);

    for (int it = 0; it < NIT; it++) {
        int buf = it & 1;
#pragma unroll
        for (int i = 0; i < 4; i++) {
            float f[4] = {ra[i].x, ra[i].y, ra[i].z, ra[i].w};
            __half h[4];
#pragma unroll
            for (int j = 0; j < 4; j++) h[j] = __float2half_rn(f[j]);
            unsigned off = aStOff + 32 * i * 64;
            *(uint2*)(dynsmem + AH + buf * TILEB + off) = *(uint2*)h;
        }
        if (it + 1 < NIT) {
            loadA(it + 1, ra);
            issueB(it + 1, buf ^ 1);
            asm volatile("cp.async.commit_group;" ::);
            asm volatile("cp.async.wait_group 1;" ::);
        } else {
            asm volatile("cp.async.wait_group 0;" ::);
        }
        __syncthreads();

        unsigned ah = base + AH + buf * TILEB;
        unsigned bh = base + BH + buf * TILEB;
#pragma unroll
        for (int ks = 0; ks < 2; ks++) {
            unsigned bhf[4][4];
#pragma unroll
            for (int np = 0; np < 4; np++) ldmx4(bhf[np], bh + bOff[np][ks]);
#pragma unroll
            for (int mt = 0; mt < 2; mt++) {
                unsigned ahf[4];
                ldmx4(ahf, ah + aOff[mt][ks]);
#pragma unroll
                for (int nt = 0; nt < 8; nt++)
                    mma16816h(acc[mt][nt], ahf, &bhf[nt >> 1][(nt & 1) * 2]);
            }
        }
        __syncthreads();
    }

    int g = lane >> 2, t = lane & 3;
    // h1 writeback (fp16)
#pragma unroll
    for (int mt = 0; mt < 2; mt++) {
        int r0 = bm + wr * 32 + mt * 16 + g;
        int r1 = r0 + 8;
#pragma unroll
        for (int nt = 0; nt < 8; nt++) {
            int col = wc * 64 + nt * 8 + t * 2;
            if (r0 < NNODES)
                *(__half2*)&g_h1[(long)r0 * F1 + col] =
                    __floats2half2_rn(acc[mt][nt][0], acc[mt][nt][1]);
            if (r1 < NNODES)
                *(__half2*)&g_h1[(long)r1 * F1 + col] =
                    __floats2half2_rn(acc[mt][nt][2], acc[mt][nt][3]);
        }
    }
    // fused coeff1 (fp32 accumulators)
#pragma unroll
    for (int mt = 0; mt < 2; mt++) {
        int r0 = bm + wr * 32 + mt * 16 + g;
        int r1 = r0 + 8;
#pragma unroll
        for (int hh = 0; hh < 4; hh++) {
            float s0 = 0.f, d0 = 0.f, s1 = 0.f, d1 = 0.f;
#pragma unroll
            for (int q = 0; q < 2; q++) {
                int nt  = 2 * hh + q;
                int col = wc * 64 + nt * 8 + t * 2;
                float asv0 = __ldg(&att_s[col]), asv1 = __ldg(&att_s[col + 1]);
                float adv0 = __ldg(&att_d[col]), adv1 = __ldg(&att_d[col + 1]);
                s0 += acc[mt][nt][0] * asv0 + acc[mt][nt][1] * asv1;
                d0 += acc[mt][nt][0] * adv0 + acc[mt][nt][1] * adv1;
                s1 += acc[mt][nt][2] * asv0 + acc[mt][nt][3] * asv1;
                d1 += acc[mt][nt][2] * adv0 + acc[mt][nt][3] * adv1;
            }
#pragma unroll
            for (int o = 1; o <= 2; o <<= 1) {
                s0 += __shfl_xor_sync(0xFFFFFFFFu, s0, o);
                d0 += __shfl_xor_sync(0xFFFFFFFFu, d0, o);
                s1 += __shfl_xor_sync(0xFFFFFFFFu, s1, o);
                d1 += __shfl_xor_sync(0xFFFFFFFFu, d1, o);
            }
            if (t == 0) {
                int gh = wc * 4 + hh;
                if (r0 < NNODES) { g_as1[r0 * H1N + gh] = s0; g_ad1[r0 * H1N + gh] = d0; }
                if (r1 < NNODES) { g_as1[r1 * H1N + gh] = s1; g_ad1[r1 * H1N + gh] = d1; }
            }
        }
    }
}

// ---------------- layer-1 aggregation: fp16 gather, direct-exp softmax -----
__global__ void k_agg1(const float* __restrict__ b1, int n0, int n1) {
    int gtid = blockIdx.x * blockDim.x + threadIdx.x;
    int n    = n0 + (gtid >> 5);
    int lane = threadIdx.x & 31;
    if (n >= n1) return;
    int h = lane >> 2;
    int beg = g_rowptr[n], end = g_rowptr[n + 1];
    float adst = g_ad1[n * H1N + h];
    float s = 0.f;
    float ax = 0.f, ay = 0.f, az = 0.f, aw = 0.f;

    int   s_p2 = (beg + 1 < end) ? __ldg(&g_csr[beg + 1]) : 0;
    float e_p1 = 0.f;
    uint2 v_p1 = make_uint2(0u, 0u);
    if (beg < end) {
        int s0 = __ldg(&g_csr[beg]);
        e_p1 = g_as1[s0 * H1N + h];
        v_p1 = *(const uint2*)&g_h1[(long)s0 * F1 + lane * 4];
    }
    for (int j = beg; j < end; j++) {
        float e_c = e_p1 + adst;
        uint2 u   = v_p1;
        int s_nxt = s_p2;
        if (j + 2 < end) s_p2 = __ldg(&g_csr[j + 2]);
        if (j + 1 < end) {
            e_p1 = g_as1[s_nxt * H1N + h];
            v_p1 = *(const uint2*)&g_h1[(long)s_nxt * F1 + lane * 4];
        }
        float2 f0 = __half22float2(*(__half2*)&u.x);
        float2 f1 = __half22float2(*(__half2*)&u.y);
        float e = (e_c > 0.f) ? e_c : 0.2f * e_c;
        float w = __expf(fminf(e, 80.f));
        s  += w;
        ax += w * f0.x;
        ay += w * f0.y;
        az += w * f1.x;
        aw += w * f1.y;
    }
    float inv = 1.f / s;
    float o[4];
    o[0] = ax * inv + b1[lane * 4 + 0];
    o[1] = ay * inv + b1[lane * 4 + 1];
    o[2] = az * inv + b1[lane * 4 + 2];
    o[3] = aw * inv + b1[lane * 4 + 3];
#pragma unroll
    for (int i = 0; i < 4; i++)
        o[i] = (o[i] > 0.f) ? o[i] : (__expf(o[i]) - 1.f);
    *(float4*)&g_h1a[(long)n * F1 + lane * 4] = *(float4*)o;
}

// ---------------- GEMM2 + fused coeff2 (4x5 thread tile, 64-row blocks) ----
#define GS2_BYTES ((64 * 132 + 40 * 132 + 64 * 41) * 4)
__global__ __launch_bounds__(128) void k_gemm2(const float* __restrict__ W2,
                                               const float* __restrict__ att_s,
                                               const float* __restrict__ att_d,
                                               int n0, int n1) {
    float* hs  = (float*)dynsmem;        // [64][132]
    float* wst = hs + 64 * 132;          // [40][132]  W2 transposed
    float* h2s = wst + 40 * 132;         // [64][41]
    int r0  = n0 + blockIdx.x * 64;
    int tid = threadIdx.x;

    for (int i = tid; i < F2 * F1; i += 128) {
        int k = i / F2, c = i - k * F2;
        wst[c * 132 + k] = W2[i];
    }
    for (int i = tid; i < 64 * 32; i += 128) {
        int r = i >> 5, k4 = i & 31;
        int gr = r0 + r;
        float4 v = (gr < n1) ? *(const float4*)&g_h1a[(long)gr * F1 + k4 * 4]
                             : make_float4(0.f, 0.f, 0.f, 0.f);
        *(float4*)&hs[r * 132 + k4 * 4] = v;
    }
    __syncthreads();

    int rowg = tid >> 3;
    int colg = tid & 7;
    float acc[4][5];
#pragma unroll
    for (int i = 0; i < 4; i++)
#pragma unroll
        for (int j = 0; j < 5; j++) acc[i][j] = 0.f;

    for (int k4 = 0; k4 < 32; k4++) {
        float4 w[5];
#pragma unroll
        for (int j = 0; j < 5; j++)
            w[j] = *(float4*)&wst[(colg * 5 + j) * 132 + k4 * 4];
#pragma unroll
        for (int i = 0; i < 4; i++) {
            float4 hv = *(float4*)&hs[(rowg + 16 * i) * 132 + k4 * 4];
#pragma unroll
            for (int j = 0; j < 5; j++)
                acc[i][j] += hv.x * w[j].x + hv.y * w[j].y + hv.z * w[j].z + hv.w * w[j].w;
        }
    }
#pragma unroll
    for (int i = 0; i < 4; i++) {
        int r = rowg + 16 * i;
#pragma unroll
        for (int j = 0; j < 5; j++)
            h2s[r * 41 + colg * 5 + j] = acc[i][j];
    }
    __syncthreads();
    for (int i = tid; i < 64 * F2; i += 128) {
        int r = i / F2, c = i - r * F2;
        int gr = r0 + r;
        if (gr < n1) g_h2[(long)gr * F2 + c] = h2s[r * 41 + c];
    }
    if (tid < 64) {
        int gr = r0 + tid;
        if (gr < n1) {
            float s = 0.f, d = 0.f;
#pragma unroll
            for (int cc = 0; cc < F2; cc++) {
                float v = h2s[tid * 41 + cc];
                s += v * __ldg(&att_s[cc]);
                d += v * __ldg(&att_d[cc]);
            }
            g_as2[gr] = s;
            g_ad2[gr] = d;
        }
    }
}

// ---------------- layer-2 aggregation + bias + log_softmax (direct exp) ----
__global__ void k_agg2(const float* __restrict__ b2, float* __restrict__ out) {
    int gtid = blockIdx.x * blockDim.x + threadIdx.x;
    int n    = gtid >> 5;
    int lane = threadIdx.x & 31;
    if (n >= NNODES) return;
    bool has2 = lane < 8;
    int beg = g_rowptr[n], end = g_rowptr[n + 1];
    float adst = g_ad2[n];
    float s = 0.f, a0 = 0.f, a1 = 0.f;

    int   s_p2 = (beg + 1 < end) ? __ldg(&g_csr[beg + 1]) : 0;
    float e_p1 = 0.f, v0_p = 0.f, v1_p = 0.f;
    if (beg < end) {
        int s0 = __ldg(&g_csr[beg]);
        e_p1 = g_as2[s0];
        v0_p = g_h2[(long)s0 * F2 + lane];
        v1_p = has2 ? g_h2[(long)s0 * F2 + 32 + lane] : 0.f;
    }
    for (int j = beg; j < end; j++) {
        float e_c = e_p1 + adst;
        float v0 = v0_p, v1 = v1_p;
        int s_nxt = s_p2;
        if (j + 2 < end) s_p2 = __ldg(&g_csr[j + 2]);
        if (j + 1 < end) {
            e_p1 = g_as2[s_nxt];
            v0_p = g_h2[(long)s_nxt * F2 + lane];
            v1_p = has2 ? g_h2[(long)s_nxt * F2 + 32 + lane] : 0.f;
        }
        float e = (e_c > 0.f) ? e_c : 0.2f * e_c;
        float w = __expf(fminf(e, 80.f));
        s  += w;
        a0 += w * v0;
        a1 += w * v1;
    }
    float inv = 1.f / s;
    float x0 = a0 * inv + b2[lane];
    float x1 = has2 ? (a1 * inv + b2[32 + lane]) : -1e30f;
    float mx = fmaxf(x0, x1);
#pragma unroll
    for (int o = 16; o; o >>= 1) mx = fmaxf(mx, __shfl_xor_sync(0xFFFFFFFFu, mx, o));
    float se = __expf(x0 - mx) + (has2 ? __expf(x1 - mx) : 0.f);
#pragma unroll
    for (int o = 16; o; o >>= 1) se += __shfl_xor_sync(0xFFFFFFFFu, se, o);
    float lse = mx + logf(se);
    out[(long)n * F2 + lane] = x0 - lse;
    if (has2) out[(long)n * F2 + 32 + lane] = x1 - lse;
}

// ---------------- launch ----------------
extern "C" void kernel_launch(void* const* d_in, const int* in_sizes, int n_in,
                              void* d_out, int out_size) {
    const float* x   = (const float*)d_in[0];
    const int*   ei  = (const int*)d_in[1];
    const float* W1  = (const float*)d_in[2];
    const float* as1 = (const float*)d_in[3];
    const float* ad1 = (const float*)d_in[4];
    const float* b1  = (const float*)d_in[5];
    const float* W2  = (const float*)d_in[6];
    const float* as2 = (const float*)d_in[7];
    const float* ad2 = (const float*)d_in[8];
    const float* b2  = (const float*)d_in[9];
    float*       out = (float*)d_out;

    int E    = in_sizes[1] / 2;
    if (E > EMAX) E = EMAX;
    int Etot = E + NNODES;
    int nb   = (NNODES + 1023) / 1024;

    static cudaStream_t sA = nullptr, sB = nullptr;
    static cudaEvent_t  e0, eA1, eB, eA2;
    if (!sA) {
        cudaStreamCreateWithFlags(&sA, cudaStreamNonBlocking);
        cudaStreamCreateWithFlags(&sB, cudaStreamNonBlocking);
        cudaEventCreateWithFlags(&e0,  cudaEventDisableTiming);
        cudaEventCreateWithFlags(&eA1, cudaEventDisableTiming);
        cudaEventCreateWithFlags(&eB,  cudaEventDisableTiming);
        cudaEventCreateWithFlags(&eA2, cudaEventDisableTiming);
        cudaFuncSetAttribute(k_gemm1_mma, cudaFuncAttributeMaxDynamicSharedMemorySize, 4 * TILEB);
        cudaFuncSetAttribute(k_gemm2, cudaFuncAttributeMaxDynamicSharedMemorySize, GS2_BYTES);
    }

    cudaEventRecord(e0, 0);
    cudaStreamWaitEvent(sA, e0, 0);
    cudaStreamWaitEvent(sB, e0, 0);

    const int NLO = NH0;
    const int NHI = NNODES - NH0;

    // enqueue order: launch index 3 = k_gemm1_mma (ncu window)
    k_zero_counts<<<(NNODES + 255) / 256, 256, 0, sB>>>();                    // 0
    k_count<<<(Etot + 255) / 256, 256, 0, sB>>>(ei, E, Etot);                 // 1
    k_convB<<<(FIN * F1 + 255) / 256, 256, 0, sA>>>(W1);                      // 2
    k_gemm1_mma<<<(NNODES + 127) / 128, 256, 4 * TILEB, sA>>>(x, as1, ad1);   // 3 <- profiled
    cudaEventRecord(eA1, sA);
    k_scan1<<<nb, 1024, 0, sB>>>();                                           // 4
    k_scan2<<<1, 64, 0, sB>>>(nb);                                            // 5
    k_scan3<<<(NNODES + 255) / 256, 256, 0, sB>>>(Etot);                      // 6
    k_fill<<<(Etot + 255) / 256, 256, 0, sB>>>(ei, E, Etot);                  // 7
    cudaEventRecord(eB, sB);

    // stream A: hi-half aggregation + gemm2
    cudaStreamWaitEvent(sA, eB, 0);
    k_agg1<<<(NHI * 32 + 255) / 256, 256, 0, sA>>>(b1, NH0, NNODES);          // 8
    k_gemm2<<<(NHI + 63) / 64, 128, GS2_BYTES, sA>>>(W2, as2, ad2, NH0, NNODES); // 9
    cudaEventRecord(eA2, sA);

    // default stream: lo-half aggregation + gemm2, then final agg2
    cudaStreamWaitEvent(0, eA1, 0);
    cudaStreamWaitEvent(0, eB, 0);
    k_agg1<<<(NLO * 32 + 255) / 256, 256>>>(b1, 0, NH0);                      // 10
    k_gemm2<<<(NLO + 63) / 64, 128, GS2_BYTES>>>(W2, as2, ad2, 0, NH0);       // 11
    cudaStreamWaitEvent(0, eA2, 0);
    k_agg2<<<(NNODES * 32 + 255) / 256, 256>>>(b2, out);                      // 12
}

// round 14
// speedup vs baseline: 1.4029x; 1.0492x over previous
#include <cuda_runtime.h>
#include <cuda_fp16.h>

#define NNODES 50000
#define FIN    512
#define H1N    8
#define C1N    16
#define F1     128      // H1*C1
#define F2     40
#define EMAX   800000
#define ETOTMAX (EMAX + NNODES)
#define NH0    25024    // lo/hi node split (64-aligned)

// ---------------- static scratch ----------------
__device__ __half g_h1 [NNODES * F1];   // fp16 layer1 features (gather payload)
__device__ float g_h1a[NNODES * F1];
__device__ float g_as1[NNODES * H1N];
__device__ float g_ad1[NNODES * H1N];
__device__ float g_h2 [NNODES * F2];
__device__ float g_as2[NNODES];
__device__ float g_ad2[NNODES];
__device__ int   g_counts[NNODES];
__device__ int   g_rowptr[NNODES + 1];
__device__ int   g_cursor[NNODES];
__device__ int   g_csr[ETOTMAX];
__device__ int   g_bsum[64];

__device__ __half g_Bt[F1 * FIN];   // fp16 W1, transposed [n][k]

// ---------------- CSR build ----------------
__global__ void k_zero_counts() {
    int i = blockIdx.x * blockDim.x + threadIdx.x;
    if (i < NNODES) g_counts[i] = 0;
}

__global__ void k_count(const int* __restrict__ ei, int E, int Etot) {
    int i = blockIdx.x * blockDim.x + threadIdx.x;
    if (i >= Etot) return;
    int d = (i < E) ? ei[E + i] : (i - E);
    if (d < 0 || d >= NNODES) return;
    atomicAdd(&g_counts[d], 1);
}

__global__ void k_scan1() {
    __shared__ int tmp[1024];
    int t = threadIdx.x;
    int gid = blockIdx.x * 1024 + t;
    int v = (gid < NNODES) ? g_counts[gid] : 0;
    tmp[t] = v;
    __syncthreads();
    for (int off = 1; off < 1024; off <<= 1) {
        int x = (t >= off) ? tmp[t - off] : 0;
        __syncthreads();
        tmp[t] += x;
        __syncthreads();
    }
    if (gid < NNODES) g_rowptr[gid] = tmp[t] - v;
    if (t == 1023) g_bsum[blockIdx.x] = tmp[1023];
}

__global__ void k_scan2(int nb) {
    __shared__ int sh[64];
    int t = threadIdx.x;
    int v = (t < nb) ? g_bsum[t] : 0;
    sh[t] = v;
    __syncthreads();
    for (int off = 1; off < 64; off <<= 1) {
        int x = (t >= off) ? sh[t - off] : 0;
        __syncthreads();
        sh[t] += x;
        __syncthreads();
    }
    if (t < nb) g_bsum[t] = sh[t] - v;   // exclusive
}

__global__ void k_scan3(int Etot) {
    int gid = blockIdx.x * blockDim.x + threadIdx.x;
    if (gid < NNODES) {
        int v = g_rowptr[gid] + g_bsum[gid >> 10];
        g_rowptr[gid] = v;
        g_cursor[gid] = v;
    }
    if (gid == 0) g_rowptr[NNODES] = Etot;
}

__global__ void k_fill(const int* __restrict__ ei, int E, int Etot) {
    int i = blockIdx.x * blockDim.x + threadIdx.x;
    if (i >= Etot) return;
    int s, d;
    if (i < E) { s = ei[i]; d = ei[E + i]; }
    else       { s = d = i - E; }
    if (d < 0 || d >= NNODES || s < 0 || s >= NNODES) return;
    int pos = atomicAdd(&g_cursor[d], 1);
    if (pos < ETOTMAX) g_csr[pos] = s;
}

// ---------------- fp16 convert + transpose of W1 (tiny: 128KB) -------------
__global__ void k_convB(const float* __restrict__ W1) {
    int i = blockIdx.x * blockDim.x + threadIdx.x;
    if (i >= FIN * F1) return;
    int k = i / F1, n = i % F1;
    g_Bt[n * FIN + k] = __float2half_rn(W1[i]);
}

// ---------------- GEMM1 + fused coeff1 epilogue ----------------
#define SWZ32(row, chk) ((row) * 64 + (((chk) ^ (((row) >> 1) & 3)) << 4))
#define TILEB 8192   // one 128x32 fp16 tile

__device__ __forceinline__ void ldmx4(unsigned* r, unsigned addr) {
    asm volatile("ldmatrix.sync.aligned.m8n8.x4.shared.b16 {%0,%1,%2,%3}, [%4];"
                 : "=r"(r[0]), "=r"(r[1]), "=r"(r[2]), "=r"(r[3]) : "r"(addr));
}

__device__ __forceinline__ void mma16816h(float* c, const unsigned* a, const unsigned* b) {
    asm volatile(
        "mma.sync.aligned.m16n8k16.row.col.f32.f16.f16.f32 "
        "{%0,%1,%2,%3}, {%4,%5,%6,%7}, {%8,%9}, {%0,%1,%2,%3};"
        : "+f"(c[0]), "+f"(c[1]), "+f"(c[2]), "+f"(c[3])
        : "r"(a[0]), "r"(a[1]), "r"(a[2]), "r"(a[3]), "r"(b[0]), "r"(b[1]));
}

__device__ __forceinline__ void cpasync16(unsigned saddr, const void* gaddr) {
    asm volatile("cp.async.cg.shared.global [%0], [%1], 16;"
                 :: "r"(saddr), "l"(gaddr));
}

extern __shared__ __align__(16) unsigned char dynsmem[];

__global__ __launch_bounds__(256) void k_gemm1_mma(const float* __restrict__ X,
                                                   const float* __restrict__ att_s,
                                                   const float* __restrict__ att_d) {
    const int AH = 0, BH = 2 * TILEB;
    unsigned base = (unsigned)__cvta_generic_to_shared(dynsmem);

    int tid  = threadIdx.x;
    int lane = tid & 31;
    int wid  = tid >> 5;
    int wr   = wid & 3;
    int wc   = wid >> 2;
    int bm   = blockIdx.x * 128;

    int arow = tid >> 3;
    int acol = (tid & 7) * 4;
    bool av[4];
    long gA[4];
#pragma unroll
    for (int i = 0; i < 4; i++) {
        int r = bm + arow + 32 * i;
        av[i] = r < NNODES;
        gA[i] = (long)r * FIN;
    }
    unsigned aStOff = SWZ32(arow, acol >> 3) + ((acol & 4) << 1);

    int lrow = tid >> 2, lchk = tid & 3;
    unsigned sBo0 = SWZ32(lrow, lchk), sBo1 = SWZ32(lrow + 64, lchk);

    int sub = lane >> 3, r8 = lane & 7;
    unsigned aOff[2][2], bOff[4][2];
#pragma unroll
    for (int mt = 0; mt < 2; mt++) {
        int row = wr * 32 + mt * 16 + (sub & 1) * 8 + r8;
#pragma unroll
        for (int ks = 0; ks < 2; ks++)
            aOff[mt][ks] = SWZ32(row, (sub >> 1) + 2 * ks);
    }
#pragma unroll
    for (int np = 0; np < 4; np++) {
        int row = wc * 64 + np * 16 + (sub >> 1) * 8 + r8;
#pragma unroll
        for (int ks = 0; ks < 2; ks++)
            bOff[np][ks] = SWZ32(row, (sub & 1) + 2 * ks);
    }

    float acc[2][8][4];
#pragma unroll
    for (int mt = 0; mt < 2; mt++)
#pragma unroll
        for (int nt = 0; nt < 8; nt++)
#pragma unroll
            for (int j = 0; j < 4; j++) acc[mt][nt][j] = 0.f;

    const int NIT = FIN / 32;   // 16

    auto issueB = [&](int it, int b) {
        int koff = it * 32;
        cpasync16(base + BH + b * TILEB + sBo0, &g_Bt[(long)lrow * FIN + koff + lchk * 8]);
        cpasync16(base + BH + b * TILEB + sBo1, &g_Bt[(long)(lrow + 64) * FIN + koff + lchk * 8]);
    };
    auto loadA = [&](int it, float4* ra) {
        int koff = it * 32 + acol;
#pragma unroll
        for (int i = 0; i < 4; i++)
            ra[i] = av[i] ? *(const float4*)&X[gA[i] + koff]
                          : make_float4(0.f, 0.f, 0.f, 0.f);
    };

    float4 ra[4];
    issueB(0, 0);
    asm volatile("cp.async.commit_group;" ::);
    loadA(0, ra);

    for (int it = 0; it < NIT; it++) {
        int buf = it & 1;
#pragma unroll
        for (int i = 0; i < 4; i++) {
            float f[4] = {ra[i].x, ra[i].y, ra[i].z, ra[i].w};
            __half h[4];
#pragma unroll
            for (int j = 0; j < 4; j++) h[j] = __float2half_rn(f[j]);
            unsigned off = aStOff + 32 * i * 64;
            *(uint2*)(dynsmem + AH + buf * TILEB + off) = *(uint2*)h;
        }
        if (it + 1 < NIT) {
            loadA(it + 1, ra);
            issueB(it + 1, buf ^ 1);
            asm volatile("cp.async.commit_group;" ::);
            asm volatile("cp.async.wait_group 1;" ::);
        } else {
            asm volatile("cp.async.wait_group 0;" ::);
        }
        __syncthreads();

        unsigned ah = base + AH + buf * TILEB;
        unsigned bh = base + BH + buf * TILEB;
#pragma unroll
        for (int ks = 0; ks < 2; ks++) {
            unsigned bhf[4][4];
#pragma unroll
            for (int np = 0; np < 4; np++) ldmx4(bhf[np], bh + bOff[np][ks]);
#pragma unroll
            for (int mt = 0; mt < 2; mt++) {
                unsigned ahf[4];
                ldmx4(ahf, ah + aOff[mt][ks]);
#pragma unroll
                for (int nt = 0; nt < 8; nt++)
                    mma16816h(acc[mt][nt], ahf, &bhf[nt >> 1][(nt & 1) * 2]);
            }
        }
        __syncthreads();
    }

    int g = lane >> 2, t = lane & 3;
    // h1 writeback (fp16)
#pragma unroll
    for (int mt = 0; mt < 2; mt++) {
        int r0 = bm + wr * 32 + mt * 16 + g;
        int r1 = r0 + 8;
#pragma unroll
        for (int nt = 0; nt < 8; nt++) {
            int col = wc * 64 + nt * 8 + t * 2;
            if (r0 < NNODES)
                *(__half2*)&g_h1[(long)r0 * F1 + col] =
                    __floats2half2_rn(acc[mt][nt][0], acc[mt][nt][1]);
            if (r1 < NNODES)
                *(__half2*)&g_h1[(long)r1 * F1 + col] =
                    __floats2half2_rn(acc[mt][nt][2], acc[mt][nt][3]);
        }
    }
    // fused coeff1 (fp32 accumulators)
#pragma unroll
    for (int mt = 0; mt < 2; mt++) {
        int r0 = bm + wr * 32 + mt * 16 + g;
        int r1 = r0 + 8;
#pragma unroll
        for (int hh = 0; hh < 4; hh++) {
            float s0 = 0.f, d0 = 0.f, s1 = 0.f, d1 = 0.f;
#pragma unroll
            for (int q = 0; q < 2; q++) {
                int nt  = 2 * hh + q;
                int col = wc * 64 + nt * 8 + t * 2;
                float asv0 = __ldg(&att_s[col]), asv1 = __ldg(&att_s[col + 1]);
                float adv0 = __ldg(&att_d[col]), adv1 = __ldg(&att_d[col + 1]);
                s0 += acc[mt][nt][0] * asv0 + acc[mt][nt][1] * asv1;
                d0 += acc[mt][nt][0] * adv0 + acc[mt][nt][1] * adv1;
                s1 += acc[mt][nt][2] * asv0 + acc[mt][nt][3] * asv1;
                d1 += acc[mt][nt][2] * adv0 + acc[mt][nt][3] * adv1;
            }
#pragma unroll
            for (int o = 1; o <= 2; o <<= 1) {
                s0 += __shfl_xor_sync(0xFFFFFFFFu, s0, o);
                d0 += __shfl_xor_sync(0xFFFFFFFFu, d0, o);
                s1 += __shfl_xor_sync(0xFFFFFFFFu, s1, o);
                d1 += __shfl_xor_sync(0xFFFFFFFFu, d1, o);
            }
            if (t == 0) {
                int gh = wc * 4 + hh;
                if (r0 < NNODES) { g_as1[r0 * H1N + gh] = s0; g_ad1[r0 * H1N + gh] = d0; }
                if (r1 < NNODES) { g_as1[r1 * H1N + gh] = s1; g_ad1[r1 * H1N + gh] = d1; }
            }
        }
    }
}

// ---------------- layer-1 aggregation: depth-2 pipeline, clamped prefetch --
__global__ void k_agg1(const float* __restrict__ b1, int n0, int n1) {
    int gtid = blockIdx.x * blockDim.x + threadIdx.x;
    int n    = n0 + (gtid >> 5);
    int lane = threadIdx.x & 31;
    if (n >= n1) return;
    int h = lane >> 2;
    int beg = g_rowptr[n], end = g_rowptr[n + 1];
    int last = end - 1;                        // every row has >=1 edge (self-loop)
    float adst = g_ad1[n * H1N + h];
    float s = 0.f;
    float ax = 0.f, ay = 0.f, az = 0.f, aw = 0.f;

    int i0 = __ldg(&g_csr[beg]);
    int i1 = __ldg(&g_csr[min(beg + 1, last)]);
    int i2 = __ldg(&g_csr[min(beg + 2, last)]);
    float e0 = g_as1[i0 * H1N + h];
    uint2 v0 = *(const uint2*)&g_h1[(long)i0 * F1 + lane * 4];
    float e1 = g_as1[i1 * H1N + h];
    uint2 v1 = *(const uint2*)&g_h1[(long)i1 * F1 + lane * 4];

    for (int j = beg; j < end; j++) {
        float e_c = e0 + adst;
        uint2 u   = v0;
        e0 = e1; v0 = v1;
        e1 = g_as1[i2 * H1N + h];
        v1 = *(const uint2*)&g_h1[(long)i2 * F1 + lane * 4];
        i2 = __ldg(&g_csr[min(j + 3, last)]);

        float2 f0 = __half22float2(*(__half2*)&u.x);
        float2 f1 = __half22float2(*(__half2*)&u.y);
        float e = (e_c > 0.f) ? e_c : 0.2f * e_c;
        float w = __expf(fminf(e, 80.f));
        s  += w;
        ax += w * f0.x;
        ay += w * f0.y;
        az += w * f1.x;
        aw += w * f1.y;
    }
    float inv = 1.f / s;
    float o[4];
    o[0] = ax * inv + b1[lane * 4 + 0];
    o[1] = ay * inv + b1[lane * 4 + 1];
    o[2] = az * inv + b1[lane * 4 + 2];
    o[3] = aw * inv + b1[lane * 4 + 3];
#pragma unroll
    for (int i = 0; i < 4; i++)
        o[i] = (o[i] > 0.f) ? o[i] : (__expf(o[i]) - 1.f);
    *(float4*)&g_h1a[(long)n * F1 + lane * 4] = *(float4*)o;
}

// ---------------- GEMM2 + fused coeff2 (4x5 thread tile, 64-row blocks) ----
#define GS2_BYTES ((64 * 132 + 40 * 132 + 64 * 41) * 4)
__global__ __launch_bounds__(128) void k_gemm2(const float* __restrict__ W2,
                                               const float* __restrict__ att_s,
                                               const float* __restrict__ att_d,
                                               int n0, int n1) {
    float* hs  = (float*)dynsmem;        // [64][132]
    float* wst = hs + 64 * 132;          // [40][132]  W2 transposed
    float* h2s = wst + 40 * 132;         // [64][41]
    int r0  = n0 + blockIdx.x * 64;
    int tid = threadIdx.x;

    for (int i = tid; i < F2 * F1; i += 128) {
        int k = i / F2, c = i - k * F2;
        wst[c * 132 + k] = W2[i];
    }
    for (int i = tid; i < 64 * 32; i += 128) {
        int r = i >> 5, k4 = i & 31;
        int gr = r0 + r;
        float4 v = (gr < n1) ? *(const float4*)&g_h1a[(long)gr * F1 + k4 * 4]
                             : make_float4(0.f, 0.f, 0.f, 0.f);
        *(float4*)&hs[r * 132 + k4 * 4] = v;
    }
    __syncthreads();

    int rowg = tid >> 3;
    int colg = tid & 7;
    float acc[4][5];
#pragma unroll
    for (int i = 0; i < 4; i++)
#pragma unroll
        for (int j = 0; j < 5; j++) acc[i][j] = 0.f;

    for (int k4 = 0; k4 < 32; k4++) {
        float4 w[5];
#pragma unroll
        for (int j = 0; j < 5; j++)
            w[j] = *(float4*)&wst[(colg * 5 + j) * 132 + k4 * 4];
#pragma unroll
        for (int i = 0; i < 4; i++) {
            float4 hv = *(float4*)&hs[(rowg + 16 * i) * 132 + k4 * 4];
#pragma unroll
            for (int j = 0; j < 5; j++)
                acc[i][j] += hv.x * w[j].x + hv.y * w[j].y + hv.z * w[j].z + hv.w * w[j].w;
        }
    }
#pragma unroll
    for (int i = 0; i < 4; i++) {
        int r = rowg + 16 * i;
#pragma unroll
        for (int j = 0; j < 5; j++)
            h2s[r * 41 + colg * 5 + j] = acc[i][j];
    }
    __syncthreads();
    for (int i = tid; i < 64 * F2; i += 128) {
        int r = i / F2, c = i - r * F2;
        int gr = r0 + r;
        if (gr < n1) g_h2[(long)gr * F2 + c] = h2s[r * 41 + c];
    }
    if (tid < 64) {
        int gr = r0 + tid;
        if (gr < n1) {
            float s = 0.f, d = 0.f;
#pragma unroll
            for (int cc = 0; cc < F2; cc++) {
                float v = h2s[tid * 41 + cc];
                s += v * __ldg(&att_s[cc]);
                d += v * __ldg(&att_d[cc]);
            }
            g_as2[gr] = s;
            g_ad2[gr] = d;
        }
    }
}

// ---------------- layer-2 aggregation + bias + log_softmax -----------------
__global__ void k_agg2(const float* __restrict__ b2, float* __restrict__ out) {
    int gtid = blockIdx.x * blockDim.x + threadIdx.x;
    int n    = gtid >> 5;
    int lane = threadIdx.x & 31;
    if (n >= NNODES) return;
    bool has2 = lane < 8;
    int beg = g_rowptr[n], end = g_rowptr[n + 1];
    int last = end - 1;
    float adst = g_ad2[n];
    float s = 0.f, a0 = 0.f, a1 = 0.f;

    int i0 = __ldg(&g_csr[beg]);
    int i1 = __ldg(&g_csr[min(beg + 1, last)]);
    int i2 = __ldg(&g_csr[min(beg + 2, last)]);
    float e0 = g_as2[i0];
    float p0 = g_h2[(long)i0 * F2 + lane];
    float q0 = has2 ? g_h2[(long)i0 * F2 + 32 + lane] : 0.f;
    float e1 = g_as2[i1];
    float p1 = g_h2[(long)i1 * F2 + lane];
    float q1 = has2 ? g_h2[(long)i1 * F2 + 32 + lane] : 0.f;

    for (int j = beg; j < end; j++) {
        float e_c = e0 + adst;
        float v0 = p0, v1 = q0;
        e0 = e1; p0 = p1; q0 = q1;
        e1 = g_as2[i2];
        p1 = g_h2[(long)i2 * F2 + lane];
        q1 = has2 ? g_h2[(long)i2 * F2 + 32 + lane] : 0.f;
        i2 = __ldg(&g_csr[min(j + 3, last)]);

        float e = (e_c > 0.f) ? e_c : 0.2f * e_c;
        float w = __expf(fminf(e, 80.f));
        s  += w;
        a0 += w * v0;
        a1 += w * v1;
    }
    float inv = 1.f / s;
    float x0 = a0 * inv + b2[lane];
    float x1 = has2 ? (a1 * inv + b2[32 + lane]) : -1e30f;
    float mx = fmaxf(x0, x1);
#pragma unroll
    for (int o = 16; o; o >>= 1) mx = fmaxf(mx, __shfl_xor_sync(0xFFFFFFFFu, mx, o));
    float se = __expf(x0 - mx) + (has2 ? __expf(x1 - mx) : 0.f);
#pragma unroll
    for (int o = 16; o; o >>= 1) se += __shfl_xor_sync(0xFFFFFFFFu, se, o);
    float lse = mx + logf(se);
    out[(long)n * F2 + lane] = x0 - lse;
    if (has2) out[(long)n * F2 + 32 + lane] = x1 - lse;
}

// ---------------- launch ----------------
extern "C" void kernel_launch(void* const* d_in, const int* in_sizes, int n_in,
                              void* d_out, int out_size) {
    const float* x   = (const float*)d_in[0];
    const int*   ei  = (const int*)d_in[1];
    const float* W1  = (const float*)d_in[2];
    const float* as1 = (const float*)d_in[3];
    const float* ad1 = (const float*)d_in[4];
    const float* b1  = (const float*)d_in[5];
    const float* W2  = (const float*)d_in[6];
    const float* as2 = (const float*)d_in[7];
    const float* ad2 = (const float*)d_in[8];
    const float* b2  = (const float*)d_in[9];
    float*       out = (float*)d_out;

    int E    = in_sizes[1] / 2;
    if (E > EMAX) E = EMAX;
    int Etot = E + NNODES;
    int nb   = (NNODES + 1023) / 1024;

    static cudaStream_t sA = nullptr, sB = nullptr, sC = nullptr;
    static cudaEvent_t  e0, eA1, eB, eA2, eC;
    if (!sA) {
        cudaStreamCreateWithFlags(&sA, cudaStreamNonBlocking);
        cudaStreamCreateWithFlags(&sB, cudaStreamNonBlocking);
        cudaStreamCreateWithFlags(&sC, cudaStreamNonBlocking);
        cudaEventCreateWithFlags(&e0,  cudaEventDisableTiming);
        cudaEventCreateWithFlags(&eA1, cudaEventDisableTiming);
        cudaEventCreateWithFlags(&eB,  cudaEventDisableTiming);
        cudaEventCreateWithFlags(&eA2, cudaEventDisableTiming);
        cudaEventCreateWithFlags(&eC,  cudaEventDisableTiming);
        cudaFuncSetAttribute(k_gemm1_mma, cudaFuncAttributeMaxDynamicSharedMemorySize, 4 * TILEB);
        cudaFuncSetAttribute(k_gemm2, cudaFuncAttributeMaxDynamicSharedMemorySize, GS2_BYTES);
    }

    cudaEventRecord(e0, 0);
    cudaStreamWaitEvent(sA, e0, 0);
    cudaStreamWaitEvent(sB, e0, 0);
    cudaStreamWaitEvent(sC, e0, 0);

    const int NLO = NH0;
    const int NHI = NNODES - NH0;

    // enqueue order: launch index 3 = k_gemm1_mma (ncu window)
    k_zero_counts<<<(NNODES + 255) / 256, 256, 0, sB>>>();                    // 0
    k_count<<<(Etot + 255) / 256, 256, 0, sB>>>(ei, E, Etot);                 // 1
    k_convB<<<(FIN * F1 + 255) / 256, 256, 0, sA>>>(W1);                      // 2
    k_gemm1_mma<<<(NNODES + 127) / 128, 256, 4 * TILEB, sA>>>(x, as1, ad1);   // 3 <- profiled
    cudaEventRecord(eA1, sA);
    k_scan1<<<nb, 1024, 0, sB>>>();                                           // 4
    k_scan2<<<1, 64, 0, sB>>>(nb);                                            // 5
    k_scan3<<<(NNODES + 255) / 256, 256, 0, sB>>>(Etot);                      // 6
    k_fill<<<(Etot + 255) / 256, 256, 0, sB>>>(ei, E, Etot);                  // 7
    cudaEventRecord(eB, sB);

    // stream A: hi-half aggregation + gemm2
    cudaStreamWaitEvent(sA, eB, 0);
    k_agg1<<<(NHI * 32 + 255) / 256, 256, 0, sA>>>(b1, NH0, NNODES);          // 8
    k_gemm2<<<(NHI + 63) / 64, 128, GS2_BYTES, sA>>>(W2, as2, ad2, NH0, NNODES); // 9
    cudaEventRecord(eA2, sA);

    // stream C: lo-half aggregation + gemm2 (explicit stream, no legacy sync)
    cudaStreamWaitEvent(sC, eA1, 0);
    cudaStreamWaitEvent(sC, eB, 0);
    k_agg1<<<(NLO * 32 + 255) / 256, 256, 0, sC>>>(b1, 0, NH0);               // 10
    k_gemm2<<<(NLO + 63) / 64, 128, GS2_BYTES, sC>>>(W2, as2, ad2, 0, NH0);   // 11
    cudaEventRecord(eC, sC);

    // join on stream 0 for the final kernel
    cudaStreamWaitEvent(0, eA2, 0);
    cudaStreamWaitEvent(0, eC, 0);
    k_agg2<<<(NNODES * 32 + 255) / 256, 256>>>(b2, out);                      // 12
}